// round 4
// baseline (speedup 1.0000x reference)
#include <cuda_runtime.h>
#include <cuda_bf16.h>
#include <mma.h>
#include <cstdint>

using namespace nvcuda;

#define THREADS 384
#define N_TOK   64
#define DIM     96
#define HEADS   6
#define HD      16

// ---------------- device-global prepped data ----------------
__device__ __nv_bfloat16 g_qwh[96 * 288];
__device__ __nv_bfloat16 g_qwl[96 * 288];
__device__ __nv_bfloat16 g_pwh[96 * 96];
__device__ __nv_bfloat16 g_pwl[96 * 96];
__device__ float         g_bias[HEADS * 64 * 64];   // [h][n][m]

// ---------------- smem layout (bytes) ----------------
// XH/XL:  x (later attn-out O) bf16 hi/lo [64][96]
#define XH_OFF    0u
#define XL_OFF    12288u
// QKVH/QKVL: q|k|v bf16 hi/lo [192][96]  (rows: q 0-63, k 64-127, v 128-191)
#define QKVH_OFF  24576u
#define QKVL_OFF  61440u
// UNION region: W staging (hi 18432 + lo 18432) OR P hi/lo (27648 each)
#define WH_OFF    98304u
#define WL_OFF    116736u
#define PH_OFF    98304u
#define PL_OFF    125952u
// S3: f32 scores [3][64][68] (also GEMM accumulate staging [64][100])
#define S3_OFF    153600u
// MS: f32 mask [64][68]
#define MS_OFF    205824u
#define SMEM_BYTES 223232u

#define S3_HPITCH 4352   // 64*68 floats per head
#define SPITCH    68
#define PPITCH    72
#define STG_PITCH 100    // GEMM accumulate staging pitch (f32)

__device__ __forceinline__ void bf16_split(float v, __nv_bfloat16& hi, __nv_bfloat16& lo) {
    hi = __float2bfloat16_rn(v);
    lo = __float2bfloat16_rn(v - __bfloat162float(hi));
}

// ---------------- prep kernel: split weights, gather bias table ----------------
__global__ void __launch_bounds__(256)
prep_kernel(const float* __restrict__ qkv_w, const float* __restrict__ proj_w,
            const float* __restrict__ rpb, const int* __restrict__ ridx)
{
    int idx = blockIdx.x * 256 + threadIdx.x;
    if (idx < 96 * 288) {
        bf16_split(qkv_w[idx], g_qwh[idx], g_qwl[idx]);
    } else if (idx < 96 * 288 + 96 * 96) {
        int j = idx - 96 * 288;
        bf16_split(proj_w[j], g_pwh[j], g_pwl[j]);
    } else if (idx < 96 * 288 + 96 * 96 + HEADS * 4096) {
        int j = idx - (96 * 288 + 96 * 96);
        int h = j >> 12, r = (j >> 6) & 63, m = j & 63;
        g_bias[j] = rpb[ridx[r * 64 + m] * HEADS + h];
    }
}

extern __shared__ char smc[];

typedef wmma::fragment<wmma::matrix_a, 16, 16, 16, __nv_bfloat16, wmma::row_major> FragA;
typedef wmma::fragment<wmma::matrix_b, 16, 16, 16, __nv_bfloat16, wmma::row_major> FragB;
typedef wmma::fragment<wmma::matrix_b, 16, 16, 16, __nv_bfloat16, wmma::col_major> FragBT;
typedef wmma::fragment<wmma::accumulator, 16, 16, 16, float> FragC;

__global__ void __launch_bounds__(THREADS, 1)
win_attn_wmma(const float* __restrict__ x,
              const float* __restrict__ mask,
              const float* __restrict__ qkv_b,
              const float* __restrict__ proj_b,
              float* __restrict__ out,
              int nW)
{
    const int t   = threadIdx.x;
    const int wid = t >> 5;
    const int b   = blockIdx.x;

    __nv_bfloat16* XH   = (__nv_bfloat16*)(smc + XH_OFF);
    __nv_bfloat16* XL   = (__nv_bfloat16*)(smc + XL_OFF);
    __nv_bfloat16* QKVH = (__nv_bfloat16*)(smc + QKVH_OFF);
    __nv_bfloat16* QKVL = (__nv_bfloat16*)(smc + QKVL_OFF);
    __nv_bfloat16* WH   = (__nv_bfloat16*)(smc + WH_OFF);
    __nv_bfloat16* WL   = (__nv_bfloat16*)(smc + WL_OFF);
    __nv_bfloat16* PH   = (__nv_bfloat16*)(smc + PH_OFF);
    __nv_bfloat16* PL   = (__nv_bfloat16*)(smc + PL_OFF);
    float*         S3   = (float*)(smc + S3_OFF);
    float*         STG  = (float*)(smc + S3_OFF);     // alias
    float*         MS   = (float*)(smc + MS_OFF);

    // ---- stage x (split) and mask ----
    {
        const float* xb = x + (size_t)b * (N_TOK * DIM);
        #pragma unroll
        for (int i = 0; i < 16; i++) {
            int e = t + i * THREADS;              // 6144
            float v = xb[e];
            bf16_split(v, XH[e], XL[e]);          // layout [row][96] contiguous
        }
        const float* mb = mask + (size_t)(b % nW) * (N_TOK * N_TOK);
        #pragma unroll
        for (int i = 0; i < 11; i++) {
            int e = t + i * THREADS;
            if (e < 4096) {
                int n = e >> 6, m = e & 63;
                MS[n * SPITCH + m] = mb[e];
            }
        }
    }

    // ---- qkv GEMM: 3 slices of (64x96)@(96x96) ----
    const int mt  = wid & 3;            // m tile 0..3
    const int ng  = wid >> 2;           // 0..2
    const int nt0 = ng * 2;             // n tiles nt0, nt0+1 (of 6)

    #pragma unroll 1
    for (int s = 0; s < 3; s++) {
        // stage W slice (bf16 copy, uint32 granularity)
        {
            const uint32_t* sh = (const uint32_t*)(g_qwh);
            const uint32_t* sl = (const uint32_t*)(g_qwl);
            uint32_t* dh = (uint32_t*)WH;
            uint32_t* dl = (uint32_t*)WL;
            #pragma unroll
            for (int i = 0; i < 12; i++) {
                int e = t + i * THREADS;          // 4608 u32 = 9216 bf16
                int k = (e * 2) / 96, n = (e * 2) % 96;
                int src = (k * 288 + s * 96 + n) >> 1;
                dh[e] = sh[src];
                dl[e] = sl[src];
            }
        }
        __syncthreads();
        {
            FragC acc[2];
            wmma::fill_fragment(acc[0], 0.0f);
            wmma::fill_fragment(acc[1], 0.0f);
            FragA ah, al;
            FragB bh, bl;
            #pragma unroll 1
            for (int k = 0; k < 6; k++) {
                wmma::load_matrix_sync(ah, XH + (mt * 16) * 96 + k * 16, 96);
                wmma::load_matrix_sync(al, XL + (mt * 16) * 96 + k * 16, 96);
                #pragma unroll
                for (int j = 0; j < 2; j++) {
                    wmma::load_matrix_sync(bh, WH + (k * 16) * 96 + (nt0 + j) * 16, 96);
                    wmma::load_matrix_sync(bl, WL + (k * 16) * 96 + (nt0 + j) * 16, 96);
                    wmma::mma_sync(acc[j], ah, bh, acc[j]);
                    wmma::mma_sync(acc[j], ah, bl, acc[j]);
                    wmma::mma_sync(acc[j], al, bh, acc[j]);
                }
            }
            #pragma unroll
            for (int j = 0; j < 2; j++)
                wmma::store_matrix_sync(STG + (mt * 16) * STG_PITCH + (nt0 + j) * 16,
                                        acc[j], STG_PITCH, wmma::mem_row_major);
        }
        __syncthreads();
        // epilogue: +bias, (scale q), split to QKV hi/lo
        {
            const float sc = (s == 0) ? 0.25f : 1.0f;
            #pragma unroll
            for (int i = 0; i < 16; i++) {
                int e = t + i * THREADS;          // 6144
                int r = e / 96, c = e % 96;
                float v = (STG[r * STG_PITCH + c] + qkv_b[s * 96 + c]) * sc;
                int d = (s * 64 + r) * 96 + c;
                bf16_split(v, QKVH[d], QKVL[d]);
            }
        }
        __syncthreads();
    }

    // ---- attention: 2 groups of 3 heads ----
    #pragma unroll 1
    for (int g = 0; g < 2; g++) {
        // S = Q @ K^T  (48 tiles, 4 per warp)
        {
            FragA qh, ql;
            FragBT kh, kl;
            FragC acc;
            #pragma unroll
            for (int j = 0; j < 4; j++) {
                int tile = wid * 4 + j;
                int hl = tile >> 4, r = tile & 15;
                int smt = r >> 2, snt = r & 3;
                int h = g * 3 + hl;
                wmma::load_matrix_sync(qh, QKVH + (smt * 16) * 96 + h * HD, 96);
                wmma::load_matrix_sync(ql, QKVL + (smt * 16) * 96 + h * HD, 96);
                wmma::load_matrix_sync(kh, QKVH + (64 + snt * 16) * 96 + h * HD, 96);
                wmma::load_matrix_sync(kl, QKVL + (64 + snt * 16) * 96 + h * HD, 96);
                wmma::fill_fragment(acc, 0.0f);
                wmma::mma_sync(acc, qh, kh, acc);
                wmma::mma_sync(acc, qh, kl, acc);
                wmma::mma_sync(acc, ql, kh, acc);
                wmma::store_matrix_sync(S3 + hl * S3_HPITCH + (smt * 16) * SPITCH + snt * 16,
                                        acc, SPITCH, wmma::mem_row_major);
            }
        }
        __syncthreads();
        // softmax (+bias from gmem, +mask), write P hi/lo
        if (t < 192) {
            int hl = t >> 6, n = t & 63;
            const float* srow = S3 + hl * S3_HPITCH + n * SPITCH;
            const float* brow = g_bias + ((size_t)(g * 3 + hl) * 64 + n) * 64;
            const float* mrow = MS + n * SPITCH;
            float sc[64], mx = -1e30f;
            #pragma unroll
            for (int m = 0; m < 64; m++) {
                float v = srow[m] + brow[m] + mrow[m];
                sc[m] = v;
                mx = fmaxf(mx, v);
            }
            float sum = 0.f;
            #pragma unroll
            for (int m = 0; m < 64; m++) {
                float e = __expf(sc[m] - mx);
                sc[m] = e; sum += e;
            }
            float inv = 1.f / sum;
            __nv_bfloat16* phr = PH + (hl * 64 + n) * PPITCH;
            __nv_bfloat16* plr = PL + (hl * 64 + n) * PPITCH;
            #pragma unroll
            for (int m = 0; m < 64; m++) {
                float p = sc[m] * inv;
                __nv_bfloat16 hi, lo;
                bf16_split(p, hi, lo);
                phr[m] = hi; plr[m] = lo;
            }
        }
        __syncthreads();
        // PV: O_h[64x16] = P[64x64] @ V[64x16]  (12 tiles, 1 per warp)
        {
            int hl = wid >> 2, pmt = wid & 3;
            int h = g * 3 + hl;
            FragA ph_f, pl_f;
            FragB vh, vl;
            FragC acc;
            wmma::fill_fragment(acc, 0.0f);
            #pragma unroll
            for (int kk = 0; kk < 4; kk++) {
                wmma::load_matrix_sync(ph_f, PH + (hl * 64 + pmt * 16) * PPITCH + kk * 16, PPITCH);
                wmma::load_matrix_sync(pl_f, PL + (hl * 64 + pmt * 16) * PPITCH + kk * 16, PPITCH);
                wmma::load_matrix_sync(vh, QKVH + (128 + kk * 16) * 96 + h * HD, 96);
                wmma::load_matrix_sync(vl, QKVL + (128 + kk * 16) * 96 + h * HD, 96);
                wmma::mma_sync(acc, ph_f, vh, acc);
                wmma::mma_sync(acc, ph_f, vl, acc);
                wmma::mma_sync(acc, pl_f, vh, acc);
            }
            wmma::store_matrix_sync(S3 + hl * S3_HPITCH + (pmt * 16) * SPITCH,
                                    acc, SPITCH, wmma::mem_row_major);
        }
        __syncthreads();
        // convert O group -> XH/XL (x dead): 3072 elems
        {
            #pragma unroll
            for (int i = 0; i < 8; i++) {
                int e = t + i * THREADS;              // 3072
                int hl = e >> 10, rem = e & 1023;
                int r = rem >> 4, c = rem & 15;
                float v = S3[hl * S3_HPITCH + r * SPITCH + c];
                int d = r * 96 + g * 48 + hl * 16 + c;
                bf16_split(v, XH[d], XL[d]);
            }
        }
        __syncthreads();
    }

    // ---- proj GEMM: (64x96)@(96x96) ----
    {
        const uint32_t* sh = (const uint32_t*)(g_pwh);
        const uint32_t* sl = (const uint32_t*)(g_pwl);
        uint32_t* dh = (uint32_t*)WH;
        uint32_t* dl = (uint32_t*)WL;
        #pragma unroll
        for (int i = 0; i < 12; i++) {
            int e = t + i * THREADS;                  // 4608 u32
            dh[e] = sh[e];
            dl[e] = sl[e];
        }
    }
    __syncthreads();
    {
        FragC acc[2];
        wmma::fill_fragment(acc[0], 0.0f);
        wmma::fill_fragment(acc[1], 0.0f);
        FragA ah, al;
        FragB bh, bl;
        #pragma unroll 1
        for (int k = 0; k < 6; k++) {
            wmma::load_matrix_sync(ah, XH + (mt * 16) * 96 + k * 16, 96);
            wmma::load_matrix_sync(al, XL + (mt * 16) * 96 + k * 16, 96);
            #pragma unroll
            for (int j = 0; j < 2; j++) {
                wmma::load_matrix_sync(bh, WH + (k * 16) * 96 + (nt0 + j) * 16, 96);
                wmma::load_matrix_sync(bl, WL + (k * 16) * 96 + (nt0 + j) * 16, 96);
                wmma::mma_sync(acc[j], ah, bh, acc[j]);
                wmma::mma_sync(acc[j], ah, bl, acc[j]);
                wmma::mma_sync(acc[j], al, bh, acc[j]);
            }
        }
        #pragma unroll
        for (int j = 0; j < 2; j++)
            wmma::store_matrix_sync(STG + (mt * 16) * STG_PITCH + (nt0 + j) * 16,
                                    acc[j], STG_PITCH, wmma::mem_row_major);
    }
    __syncthreads();
    {
        float* ob = out + (size_t)b * (N_TOK * DIM);
        #pragma unroll
        for (int i = 0; i < 16; i++) {
            int e = t + i * THREADS;                  // 6144
            int r = e / 96, c = e % 96;
            ob[e] = STG[r * STG_PITCH + c] + proj_b[c];
        }
    }
}

extern "C" void kernel_launch(void* const* d_in, const int* in_sizes, int n_in,
                              void* d_out, int out_size) {
    const float* x      = (const float*)d_in[0];
    const float* mask   = (const float*)d_in[1];
    const float* qkv_w  = (const float*)d_in[2];
    const float* qkv_b  = (const float*)d_in[3];
    const float* proj_w = (const float*)d_in[4];
    const float* proj_b = (const float*)d_in[5];
    const float* rpb    = (const float*)d_in[6];
    const int*   ridx   = (const int*)d_in[7];
    float* out = (float*)d_out;

    const int B_ = in_sizes[0] / (N_TOK * DIM);        // 8192
    const int nW = in_sizes[1] / (N_TOK * N_TOK);      // 512

    int prep_elems = 96 * 288 + 96 * 96 + HEADS * 4096;
    prep_kernel<<<(prep_elems + 255) / 256, 256>>>(qkv_w, proj_w, rpb, ridx);

    cudaFuncSetAttribute(win_attn_wmma,
                         cudaFuncAttributeMaxDynamicSharedMemorySize, SMEM_BYTES);
    win_attn_wmma<<<B_, THREADS, SMEM_BYTES>>>(x, mask, qkv_b, proj_b, out, nW);
}

// round 6
// speedup vs baseline: 3.2531x; 3.2531x over previous
#include <cuda_runtime.h>
#include <cuda_bf16.h>
#include <cstdint>

#define THREADS 384
#define N_TOK   64
#define DIM     96
#define HEADS   6

#define PITCHB  208u    // bytes per smem row (104 bf16; 13*16B, conflict-free LDSM)

// ---- smem byte offsets ----
#define XH_OFF   0u          // x / attn-out hi  [64][104]b16  = 13312
#define XL_OFF   13312u      // lo
#define QH_OFF   26624u      // q|k|v hi [192][104]           = 39936
#define QL_OFF   66560u
#define WTH_OFF  106496u     // weight-slice^T hi [96][104]   = 19968
#define WTL_OFF  126464u
#define BQ_OFF   146432u     // qkv_b 288 f32
#define BP_OFF   147584u     // proj_b 96 f32
#define SMEM_BYTES 147968u

// ---- prepped globals ----
__device__ __nv_bfloat16 g_qwth[3 * 96 * 96];   // [slice][n][k]
__device__ __nv_bfloat16 g_qwtl[3 * 96 * 96];
__device__ __nv_bfloat16 g_pwth[96 * 96];       // [n][k]
__device__ __nv_bfloat16 g_pwtl[96 * 96];
__device__ float         g_bias[HEADS * 64 * 64]; // [h][n][m]

__device__ __forceinline__ void bsplit(float v, __nv_bfloat16& h, __nv_bfloat16& l) {
    h = __float2bfloat16_rn(v);
    l = __float2bfloat16_rn(v - __bfloat162float(h));
}

__global__ void __launch_bounds__(256)
prep_kernel(const float* __restrict__ qkv_w, const float* __restrict__ proj_w,
            const float* __restrict__ rpb, const int* __restrict__ ridx)
{
    int idx = blockIdx.x * 256 + threadIdx.x;
    if (idx < 27648) {
        int s = idx / 9216, rem = idx % 9216, n = rem / 96, k = rem % 96;
        bsplit(qkv_w[k * 288 + s * 96 + n], g_qwth[idx], g_qwtl[idx]);
    } else if (idx < 27648 + 9216) {
        int j = idx - 27648, n = j / 96, k = j % 96;
        bsplit(proj_w[k * 96 + n], g_pwth[j], g_pwtl[j]);
    } else if (idx < 27648 + 9216 + 24576) {
        int j = idx - 36864;
        int h = j >> 12, r = (j >> 6) & 63, m = j & 63;
        g_bias[j] = rpb[ridx[r * 64 + m] * HEADS + h];
    }
}

// ---- PTX helpers ----
__device__ __forceinline__ uint32_t smem_u32(const void* p) {
    uint32_t a;
    asm("{ .reg .u64 t; cvta.to.shared.u64 t, %1; cvt.u32.u64 %0, t; }" : "=r"(a) : "l"(p));
    return a;
}
__device__ __forceinline__ void ldsm_x4(uint32_t* r, uint32_t a) {
    asm volatile("ldmatrix.sync.aligned.m8n8.x4.shared.b16 {%0,%1,%2,%3}, [%4];"
        : "=r"(r[0]), "=r"(r[1]), "=r"(r[2]), "=r"(r[3]) : "r"(a));
}
__device__ __forceinline__ void ldsm_x2(uint32_t* r, uint32_t a) {
    asm volatile("ldmatrix.sync.aligned.m8n8.x2.shared.b16 {%0,%1}, [%2];"
        : "=r"(r[0]), "=r"(r[1]) : "r"(a));
}
__device__ __forceinline__ void ldsm_x2t(uint32_t* r, uint32_t a) {
    asm volatile("ldmatrix.sync.aligned.m8n8.x2.trans.shared.b16 {%0,%1}, [%2];"
        : "=r"(r[0]), "=r"(r[1]) : "r"(a));
}
__device__ __forceinline__ void mma16816(float* c, const uint32_t* a, const uint32_t* b) {
    asm volatile("mma.sync.aligned.m16n8k16.row.col.f32.bf16.bf16.f32 "
        "{%0,%1,%2,%3}, {%4,%5,%6,%7}, {%8,%9}, {%0,%1,%2,%3};"
        : "+f"(c[0]), "+f"(c[1]), "+f"(c[2]), "+f"(c[3])
        : "r"(a[0]), "r"(a[1]), "r"(a[2]), "r"(a[3]), "r"(b[0]), "r"(b[1]));
}
__device__ __forceinline__ void split2(float v0, float v1, uint32_t& hp, uint32_t& lp) {
    __nv_bfloat16 h0, l0, h1, l1;
    bsplit(v0, h0, l0);
    bsplit(v1, h1, l1);
    __nv_bfloat162 hh, ll;
    hh.x = h0; hh.y = h1; ll.x = l0; ll.y = l1;
    hp = *reinterpret_cast<uint32_t*>(&hh);
    lp = *reinterpret_cast<uint32_t*>(&ll);
}

extern __shared__ char smc[];

__global__ void __launch_bounds__(THREADS, 1)
win_attn_mma(const float* __restrict__ x,
             const float* __restrict__ mask,
             const float* __restrict__ qkv_b,
             const float* __restrict__ proj_b,
             float* __restrict__ out,
             int nW)
{
    const int t = threadIdx.x, wid = t >> 5, lane = t & 31, b = blockIdx.x;
    const uint32_t sb = smem_u32(smc);

    // ---- stage x (bf16 split) + biases + Wt slice 0 ----
    {
        const float* xb = x + (size_t)b * 6144;
        #pragma unroll
        for (int i = 0; i < 16; i++) {
            int e = t + i * THREADS;
            int r = e / 96, c = e % 96;
            __nv_bfloat16 h, l;
            bsplit(xb[e], h, l);
            *(__nv_bfloat16*)(smc + XH_OFF + r * PITCHB + c * 2) = h;
            *(__nv_bfloat16*)(smc + XL_OFF + r * PITCHB + c * 2) = l;
        }
        if (t < 288) ((float*)(smc + BQ_OFF))[t] = qkv_b[t];
        if (t < 96)  ((float*)(smc + BP_OFF))[t] = proj_b[t];
        const uint32_t* sh = (const uint32_t*)g_qwth;
        const uint32_t* sl = (const uint32_t*)g_qwtl;
        #pragma unroll
        for (int i = 0; i < 12; i++) {
            int idx = t + i * THREADS;           // 4608 u32
            int n = idx / 48, kk = idx % 48;
            *(uint32_t*)(smc + WTH_OFF + n * PITCHB + kk * 4) = sh[idx];
            *(uint32_t*)(smc + WTL_OFF + n * PITCHB + kk * 4) = sl[idx];
        }
    }
    __syncthreads();

    const int mt = wid & 3;      // m tile
    const int ng = wid >> 2;     // n group (4 ntiles of 8)
    const float* bq = (const float*)(smc + BQ_OFF);

    // ---- qkv GEMM: 3 slices of (64x96)@(96x96) ----
    #pragma unroll 1
    for (int s = 0; s < 3; s++) {
        float acc[4][4];
        #pragma unroll
        for (int j = 0; j < 4; j++)
            { acc[j][0] = 0.f; acc[j][1] = 0.f; acc[j][2] = 0.f; acc[j][3] = 0.f; }
        #pragma unroll
        for (int kt = 0; kt < 6; kt++) {
            uint32_t ah[4], al[4];
            uint32_t ar = (uint32_t)(mt * 16 + (lane & 15)) * PITCHB
                        + (uint32_t)(kt * 16 + ((lane >> 4) << 3)) * 2;
            ldsm_x4(ah, sb + XH_OFF + ar);
            ldsm_x4(al, sb + XL_OFF + ar);
            #pragma unroll
            for (int j = 0; j < 4; j++) {
                uint32_t br = (uint32_t)((ng * 4 + j) * 8 + (lane & 7)) * PITCHB
                            + (uint32_t)(kt * 16 + ((lane >> 3) & 1) * 8) * 2;
                uint32_t bh[2], bl[2];
                ldsm_x2(bh, sb + WTH_OFF + br);
                ldsm_x2(bl, sb + WTL_OFF + br);
                mma16816(acc[j], ah, bh);
                mma16816(acc[j], ah, bl);
                mma16816(acc[j], al, bh);
            }
        }
        __syncthreads();   // ALL WT(s) reads complete before WT is overwritten below
        // epilogue in registers (+bias, scale q, split) -> QKV region (disjoint from WT)
        const float scl = (s == 0) ? 0.25f : 1.0f;
        const int r0 = mt * 16 + (lane >> 2);
        #pragma unroll
        for (int j = 0; j < 4; j++) {
            int c0 = (ng * 4 + j) * 8 + (lane & 3) * 2;
            float b0 = bq[s * 96 + c0], b1 = bq[s * 96 + c0 + 1];
            uint32_t hp, lp;
            split2((acc[j][0] + b0) * scl, (acc[j][1] + b1) * scl, hp, lp);
            uint32_t off = (uint32_t)(s * 64 + r0) * PITCHB + c0 * 2;
            *(uint32_t*)(smc + QH_OFF + off) = hp;
            *(uint32_t*)(smc + QL_OFF + off) = lp;
            split2((acc[j][2] + b0) * scl, (acc[j][3] + b1) * scl, hp, lp);
            off += 8 * PITCHB;
            *(uint32_t*)(smc + QH_OFF + off) = hp;
            *(uint32_t*)(smc + QL_OFF + off) = lp;
        }
        // stage next Wt slice (or proj Wt after the last) -- same phase as epilogue
        {
            const uint32_t* sh = (const uint32_t*)((s < 2) ? g_qwth : g_pwth);
            const uint32_t* sl = (const uint32_t*)((s < 2) ? g_qwtl : g_pwtl);
            int base = (s < 2) ? (s + 1) * 4608 : 0;
            #pragma unroll
            for (int i = 0; i < 12; i++) {
                int idx = t + i * THREADS;
                int n = idx / 48, kk = idx % 48;
                *(uint32_t*)(smc + WTH_OFF + n * PITCHB + kk * 4) = sh[base + idx];
                *(uint32_t*)(smc + WTL_OFF + n * PITCHB + kk * 4) = sl[base + idx];
            }
        }
        __syncthreads();   // staging (and epilogue) visible before next mma reads WT
    }
    // QKV + proj-Wt ready here (last loop-end barrier)

    // ---- attention: 24 units (head, mtile), 2 per warp, all in registers ----
    const float* maskb = mask + (size_t)(b % nW) * 4096;
    #pragma unroll 1
    for (int iu = 0; iu < 2; iu++) {
        const int u = wid + 12 * iu;       // 0..23
        const int h = u >> 2, amt = u & 3;
        const int r0 = amt * 16 + (lane >> 2);

        uint32_t qh[4], ql[4];
        {
            uint32_t ar = (uint32_t)(amt * 16 + (lane & 15)) * PITCHB
                        + (uint32_t)(h * 16 + ((lane >> 4) << 3)) * 2;
            ldsm_x4(qh, sb + QH_OFF + ar);
            ldsm_x4(ql, sb + QL_OFF + ar);
        }
        float s8[8][4];
        #pragma unroll
        for (int nt = 0; nt < 8; nt++) {
            s8[nt][0] = 0.f; s8[nt][1] = 0.f; s8[nt][2] = 0.f; s8[nt][3] = 0.f;
            uint32_t br = (uint32_t)(64 + nt * 8 + (lane & 7)) * PITCHB
                        + (uint32_t)(h * 16 + ((lane >> 3) & 1) * 8) * 2;
            uint32_t kh[2], kl[2];
            ldsm_x2(kh, sb + QH_OFF + br);
            ldsm_x2(kl, sb + QL_OFF + br);
            mma16816(s8[nt], qh, kh);
            mma16816(s8[nt], qh, kl);
            mma16816(s8[nt], ql, kh);
        }
        // + bias (L2) + mask (L2)
        {
            const float2* br0 = (const float2*)(g_bias + (size_t)(h * 64 + r0) * 64);
            const float2* br1 = (const float2*)(g_bias + (size_t)(h * 64 + r0 + 8) * 64);
            const float2* mr0 = (const float2*)(maskb + (size_t)r0 * 64);
            const float2* mr1 = (const float2*)(maskb + (size_t)(r0 + 8) * 64);
            int ci = lane & 3;
            #pragma unroll
            for (int nt = 0; nt < 8; nt++) {
                float2 bb = br0[nt * 4 + ci], mm = mr0[nt * 4 + ci];
                s8[nt][0] += bb.x + mm.x; s8[nt][1] += bb.y + mm.y;
                bb = br1[nt * 4 + ci]; mm = mr1[nt * 4 + ci];
                s8[nt][2] += bb.x + mm.x; s8[nt][3] += bb.y + mm.y;
            }
        }
        // softmax (register + shfl over lane%4 group)
        float mx0 = -1e30f, mx1 = -1e30f;
        #pragma unroll
        for (int nt = 0; nt < 8; nt++) {
            mx0 = fmaxf(mx0, fmaxf(s8[nt][0], s8[nt][1]));
            mx1 = fmaxf(mx1, fmaxf(s8[nt][2], s8[nt][3]));
        }
        mx0 = fmaxf(mx0, __shfl_xor_sync(0xffffffffu, mx0, 1));
        mx0 = fmaxf(mx0, __shfl_xor_sync(0xffffffffu, mx0, 2));
        mx1 = fmaxf(mx1, __shfl_xor_sync(0xffffffffu, mx1, 1));
        mx1 = fmaxf(mx1, __shfl_xor_sync(0xffffffffu, mx1, 2));
        float sum0 = 0.f, sum1 = 0.f;
        #pragma unroll
        for (int nt = 0; nt < 8; nt++) {
            s8[nt][0] = __expf(s8[nt][0] - mx0); sum0 += s8[nt][0];
            s8[nt][1] = __expf(s8[nt][1] - mx0); sum0 += s8[nt][1];
            s8[nt][2] = __expf(s8[nt][2] - mx1); sum1 += s8[nt][2];
            s8[nt][3] = __expf(s8[nt][3] - mx1); sum1 += s8[nt][3];
        }
        sum0 += __shfl_xor_sync(0xffffffffu, sum0, 1);
        sum0 += __shfl_xor_sync(0xffffffffu, sum0, 2);
        sum1 += __shfl_xor_sync(0xffffffffu, sum1, 1);
        sum1 += __shfl_xor_sync(0xffffffffu, sum1, 2);
        float inv0 = 1.f / sum0, inv1 = 1.f / sum1;
        #pragma unroll
        for (int nt = 0; nt < 8; nt++) {
            s8[nt][0] *= inv0; s8[nt][1] *= inv0;
            s8[nt][2] *= inv1; s8[nt][3] *= inv1;
        }
        // PV: O(16x16) = P(16x64) @ V(64x16), P fragments built in registers
        float o[2][4];
        o[0][0]=0.f;o[0][1]=0.f;o[0][2]=0.f;o[0][3]=0.f;
        o[1][0]=0.f;o[1][1]=0.f;o[1][2]=0.f;o[1][3]=0.f;
        #pragma unroll
        for (int kt = 0; kt < 4; kt++) {
            uint32_t pah[4], pal[4];
            split2(s8[2*kt][0],   s8[2*kt][1],   pah[0], pal[0]);
            split2(s8[2*kt][2],   s8[2*kt][3],   pah[1], pal[1]);
            split2(s8[2*kt+1][0], s8[2*kt+1][1], pah[2], pal[2]);
            split2(s8[2*kt+1][2], s8[2*kt+1][3], pah[3], pal[3]);
            #pragma unroll
            for (int nt2 = 0; nt2 < 2; nt2++) {
                uint32_t vr = (uint32_t)(128 + kt * 16 + (lane & 15)) * PITCHB
                            + (uint32_t)(h * 16 + nt2 * 8) * 2;
                uint32_t vh[2], vl[2];
                ldsm_x2t(vh, sb + QH_OFF + vr);
                ldsm_x2t(vl, sb + QL_OFF + vr);
                mma16816(o[nt2], pah, vh);
                mma16816(o[nt2], pah, vl);
                mma16816(o[nt2], pal, vh);
            }
        }
        // write O -> XH/XL (x is dead; disjoint (row,col) region per unit)
        #pragma unroll
        for (int nt2 = 0; nt2 < 2; nt2++) {
            int c0 = h * 16 + nt2 * 8 + (lane & 3) * 2;
            uint32_t hp, lp;
            split2(o[nt2][0], o[nt2][1], hp, lp);
            uint32_t off = (uint32_t)r0 * PITCHB + c0 * 2;
            *(uint32_t*)(smc + XH_OFF + off) = hp;
            *(uint32_t*)(smc + XL_OFF + off) = lp;
            split2(o[nt2][2], o[nt2][3], hp, lp);
            off += 8 * PITCHB;
            *(uint32_t*)(smc + XH_OFF + off) = hp;
            *(uint32_t*)(smc + XL_OFF + off) = lp;
        }
    }
    __syncthreads();

    // ---- proj GEMM: (64x96)@(96x96) + b -> gmem ----
    {
        float acc[4][4];
        #pragma unroll
        for (int j = 0; j < 4; j++)
            { acc[j][0] = 0.f; acc[j][1] = 0.f; acc[j][2] = 0.f; acc[j][3] = 0.f; }
        #pragma unroll
        for (int kt = 0; kt < 6; kt++) {
            uint32_t ah[4], al[4];
            uint32_t ar = (uint32_t)(mt * 16 + (lane & 15)) * PITCHB
                        + (uint32_t)(kt * 16 + ((lane >> 4) << 3)) * 2;
            ldsm_x4(ah, sb + XH_OFF + ar);
            ldsm_x4(al, sb + XL_OFF + ar);
            #pragma unroll
            for (int j = 0; j < 4; j++) {
                uint32_t br = (uint32_t)((ng * 4 + j) * 8 + (lane & 7)) * PITCHB
                            + (uint32_t)(kt * 16 + ((lane >> 3) & 1) * 8) * 2;
                uint32_t bh[2], bl[2];
                ldsm_x2(bh, sb + WTH_OFF + br);
                ldsm_x2(bl, sb + WTL_OFF + br);
                mma16816(acc[j], ah, bh);
                mma16816(acc[j], ah, bl);
                mma16816(acc[j], al, bh);
            }
        }
        const float* pb = (const float*)(smc + BP_OFF);
        float* ob = out + (size_t)b * 6144;
        const int r0 = mt * 16 + (lane >> 2);
        #pragma unroll
        for (int j = 0; j < 4; j++) {
            int c0 = (ng * 4 + j) * 8 + (lane & 3) * 2;
            float b0 = pb[c0], b1 = pb[c0 + 1];
            *(float2*)(ob + (size_t)r0 * 96 + c0) =
                make_float2(acc[j][0] + b0, acc[j][1] + b1);
            *(float2*)(ob + (size_t)(r0 + 8) * 96 + c0) =
                make_float2(acc[j][2] + b0, acc[j][3] + b1);
        }
    }
}

extern "C" void kernel_launch(void* const* d_in, const int* in_sizes, int n_in,
                              void* d_out, int out_size) {
    const float* x      = (const float*)d_in[0];
    const float* mask   = (const float*)d_in[1];
    const float* qkv_w  = (const float*)d_in[2];
    const float* qkv_b  = (const float*)d_in[3];
    const float* proj_w = (const float*)d_in[4];
    const float* proj_b = (const float*)d_in[5];
    const float* rpb    = (const float*)d_in[6];
    const int*   ridx   = (const int*)d_in[7];
    float* out = (float*)d_out;

    const int B_ = in_sizes[0] / (N_TOK * DIM);        // 8192
    const int nW = in_sizes[1] / (N_TOK * N_TOK);      // 512

    prep_kernel<<<240, 256>>>(qkv_w, proj_w, rpb, ridx);

    cudaFuncSetAttribute(win_attn_mma,
                         cudaFuncAttributeMaxDynamicSharedMemorySize, SMEM_BYTES);
    win_attn_mma<<<B_, THREADS, SMEM_BYTES>>>(x, mask, qkv_b, proj_b, out, nW);
}

// round 7
// speedup vs baseline: 3.3304x; 1.0238x over previous
#include <cuda_runtime.h>
#include <cuda_bf16.h>
#include <cstdint>

#define THREADS 384
#define N_TOK   64
#define DIM     96
#define HEADS   6

#define PITCHB  208u    // bytes per smem row (104 bf16; 13*16B, conflict-free LDSM)

// ---- smem byte offsets ----
#define XH_OFF   0u          // x / attn-out hi  [64][104]b16  = 13312
#define XL_OFF   13312u      // lo
#define QH_OFF   26624u      // q|k|v hi [192][104]           = 39936
#define QL_OFF   66560u
#define SMEM_BYTES 106496u

// ---- prepped globals: weights in mma B-fragment order ----
// g_qwf[(((s*6+kt)*12+nt)*2+plane)*32 + lane] = uint2{reg0, reg1}
__device__ uint2 g_qwf[13824];   // 3 slices * 6 kt * 12 nt * 2 planes * 32 lanes
__device__ uint2 g_pwf[4608];    // proj: 6 * 12 * 2 * 32
__device__ float g_bias[HEADS * 64 * 64]; // [h][n][m]

__device__ __forceinline__ void bsplit(float v, __nv_bfloat16& h, __nv_bfloat16& l) {
    h = __float2bfloat16_rn(v);
    l = __float2bfloat16_rn(v - __bfloat162float(h));
}
__device__ __forceinline__ uint32_t pack_plane(float a, float b, int p) {
    __nv_bfloat16 ah, al, bh, bl;
    bsplit(a, ah, al);
    bsplit(b, bh, bl);
    __nv_bfloat162 v;
    v.x = p ? al : ah;
    v.y = p ? bl : bh;
    return *reinterpret_cast<uint32_t*>(&v);
}

__global__ void __launch_bounds__(256)
prep_kernel(const float* __restrict__ qkv_w, const float* __restrict__ proj_w,
            const float* __restrict__ rpb, const int* __restrict__ ridx)
{
    int idx = blockIdx.x * 256 + threadIdx.x;
    if (idx < 13824) {
        // qkv weight fragment: B[k][n] = qkv_w[k*288 + s*96 + nc]
        int lane = idx & 31, p = (idx >> 5) & 1, nt = (idx >> 6) % 12;
        int kt = (idx / 768) % 6, s = idx / 4608;
        int nc = nt * 8 + (lane >> 2);
        int k0 = kt * 16 + (lane & 3) * 2;
        const float* wc = qkv_w + s * 96 + nc;
        uint2 r;
        r.x = pack_plane(wc[(k0)     * 288], wc[(k0 + 1) * 288], p);
        r.y = pack_plane(wc[(k0 + 8) * 288], wc[(k0 + 9) * 288], p);
        g_qwf[idx] = r;
    } else if (idx < 18432) {
        int j = idx - 13824;
        int lane = j & 31, p = (j >> 5) & 1, nt = (j >> 6) % 12, kt = j / 768;
        int nc = nt * 8 + (lane >> 2);
        int k0 = kt * 16 + (lane & 3) * 2;
        const float* wc = proj_w + nc;
        uint2 r;
        r.x = pack_plane(wc[(k0)     * 96], wc[(k0 + 1) * 96], p);
        r.y = pack_plane(wc[(k0 + 8) * 96], wc[(k0 + 9) * 96], p);
        g_pwf[j] = r;
    } else if (idx < 18432 + 24576) {
        int j = idx - 18432;
        int h = j >> 12, r = (j >> 6) & 63, m = j & 63;
        g_bias[j] = rpb[ridx[r * 64 + m] * HEADS + h];
    }
}

// ---- PTX helpers ----
__device__ __forceinline__ uint32_t smem_u32(const void* p) {
    uint32_t a;
    asm("{ .reg .u64 t; cvta.to.shared.u64 t, %1; cvt.u32.u64 %0, t; }" : "=r"(a) : "l"(p));
    return a;
}
__device__ __forceinline__ void ldsm_x4(uint32_t* r, uint32_t a) {
    asm volatile("ldmatrix.sync.aligned.m8n8.x4.shared.b16 {%0,%1,%2,%3}, [%4];"
        : "=r"(r[0]), "=r"(r[1]), "=r"(r[2]), "=r"(r[3]) : "r"(a));
}
__device__ __forceinline__ void ldsm_x2(uint32_t* r, uint32_t a) {
    asm volatile("ldmatrix.sync.aligned.m8n8.x2.shared.b16 {%0,%1}, [%2];"
        : "=r"(r[0]), "=r"(r[1]) : "r"(a));
}
__device__ __forceinline__ void ldsm_x2t(uint32_t* r, uint32_t a) {
    asm volatile("ldmatrix.sync.aligned.m8n8.x2.trans.shared.b16 {%0,%1}, [%2];"
        : "=r"(r[0]), "=r"(r[1]) : "r"(a));
}
__device__ __forceinline__ void mma16816(float* c, const uint32_t* a, const uint32_t* b) {
    asm volatile("mma.sync.aligned.m16n8k16.row.col.f32.bf16.bf16.f32 "
        "{%0,%1,%2,%3}, {%4,%5,%6,%7}, {%8,%9}, {%0,%1,%2,%3};"
        : "+f"(c[0]), "+f"(c[1]), "+f"(c[2]), "+f"(c[3])
        : "r"(a[0]), "r"(a[1]), "r"(a[2]), "r"(a[3]), "r"(b[0]), "r"(b[1]));
}
__device__ __forceinline__ void split2(float v0, float v1, uint32_t& hp, uint32_t& lp) {
    __nv_bfloat16 h0, l0, h1, l1;
    bsplit(v0, h0, l0);
    bsplit(v1, h1, l1);
    __nv_bfloat162 hh, ll;
    hh.x = h0; hh.y = h1; ll.x = l0; ll.y = l1;
    hp = *reinterpret_cast<uint32_t*>(&hh);
    lp = *reinterpret_cast<uint32_t*>(&ll);
}

extern __shared__ char smc[];

__global__ void __launch_bounds__(THREADS, 1)
win_attn_mma(const float* __restrict__ x,
             const float* __restrict__ mask,
             const float* __restrict__ qkv_b,
             const float* __restrict__ proj_b,
             float* __restrict__ out,
             int nW)
{
    const int t = threadIdx.x, wid = t >> 5, lane = t & 31, b = blockIdx.x;
    const uint32_t sb = smem_u32(smc);

    // ---- stage x (vectorized bf16 split) ----
    {
        const float4* xb4 = (const float4*)(x + (size_t)b * 6144);
        #pragma unroll
        for (int i = 0; i < 4; i++) {
            int e4 = t + i * THREADS;            // 1536 float4
            int r = e4 / 24, c4 = e4 % 24;       // 24 float4 per row
            float4 v = xb4[e4];
            uint32_t h0, l0, h1, l1;
            split2(v.x, v.y, h0, l0);
            split2(v.z, v.w, h1, l1);
            uint32_t off = (uint32_t)r * PITCHB + c4 * 8;
            *(uint32_t*)(smc + XH_OFF + off)     = h0;
            *(uint32_t*)(smc + XH_OFF + off + 4) = h1;
            *(uint32_t*)(smc + XL_OFF + off)     = l0;
            *(uint32_t*)(smc + XL_OFF + off + 4) = l1;
        }
    }
    __syncthreads();

    const int mt = wid & 3;      // m tile
    const int ng = wid >> 2;     // n group (4 ntiles of 8)

    // ---- qkv GEMM: 3 slices of (64x96)@(96x96); B fragments via LDG ----
    #pragma unroll 1
    for (int s = 0; s < 3; s++) {
        float acc[4][4];
        #pragma unroll
        for (int j = 0; j < 4; j++)
            { acc[j][0] = 0.f; acc[j][1] = 0.f; acc[j][2] = 0.f; acc[j][3] = 0.f; }
        #pragma unroll
        for (int kt = 0; kt < 6; kt++) {
            uint32_t ah[4], al[4];
            uint32_t ar = (uint32_t)(mt * 16 + (lane & 15)) * PITCHB
                        + (uint32_t)(kt * 16 + ((lane >> 4) << 3)) * 2;
            ldsm_x4(ah, sb + XH_OFF + ar);
            ldsm_x4(al, sb + XL_OFF + ar);
            #pragma unroll
            for (int j = 0; j < 4; j++) {
                int nt = ng * 4 + j;
                int fi = (((s * 6 + kt) * 12 + nt) * 2) * 32 + lane;
                uint2 bh = g_qwf[fi];
                uint2 bl = g_qwf[fi + 32];
                mma16816(acc[j], ah, (const uint32_t*)&bh);
                mma16816(acc[j], ah, (const uint32_t*)&bl);
                mma16816(acc[j], al, (const uint32_t*)&bh);
            }
        }
        // epilogue in registers (+bias, scale q, split) -> QKV region
        const float scl = (s == 0) ? 0.25f : 1.0f;
        const int r0 = mt * 16 + (lane >> 2);
        #pragma unroll
        for (int j = 0; j < 4; j++) {
            int c0 = (ng * 4 + j) * 8 + (lane & 3) * 2;
            float b0 = __ldg(qkv_b + s * 96 + c0), b1 = __ldg(qkv_b + s * 96 + c0 + 1);
            uint32_t hp, lp;
            split2((acc[j][0] + b0) * scl, (acc[j][1] + b1) * scl, hp, lp);
            uint32_t off = (uint32_t)(s * 64 + r0) * PITCHB + c0 * 2;
            *(uint32_t*)(smc + QH_OFF + off) = hp;
            *(uint32_t*)(smc + QL_OFF + off) = lp;
            split2((acc[j][2] + b0) * scl, (acc[j][3] + b1) * scl, hp, lp);
            off += 8 * PITCHB;
            *(uint32_t*)(smc + QH_OFF + off) = hp;
            *(uint32_t*)(smc + QL_OFF + off) = lp;
        }
    }
    __syncthreads();   // QKV complete

    // ---- attention: 24 units (head, mtile), 2 per warp, all in registers ----
    const float* maskb = mask + (size_t)(b % nW) * 4096;
    #pragma unroll 1
    for (int iu = 0; iu < 2; iu++) {
        const int u = wid + 12 * iu;       // 0..23
        const int h = u >> 2, amt = u & 3;
        const int r0 = amt * 16 + (lane >> 2);

        uint32_t qh[4], ql[4];
        {
            uint32_t ar = (uint32_t)(amt * 16 + (lane & 15)) * PITCHB
                        + (uint32_t)(h * 16 + ((lane >> 4) << 3)) * 2;
            ldsm_x4(qh, sb + QH_OFF + ar);
            ldsm_x4(ql, sb + QL_OFF + ar);
        }
        float s8[8][4];
        #pragma unroll
        for (int nt = 0; nt < 8; nt++) {
            s8[nt][0] = 0.f; s8[nt][1] = 0.f; s8[nt][2] = 0.f; s8[nt][3] = 0.f;
            uint32_t br = (uint32_t)(64 + nt * 8 + (lane & 7)) * PITCHB
                        + (uint32_t)(h * 16 + ((lane >> 3) & 1) * 8) * 2;
            uint32_t kh[2], kl[2];
            ldsm_x2(kh, sb + QH_OFF + br);
            ldsm_x2(kl, sb + QL_OFF + br);
            mma16816(s8[nt], qh, kh);
            mma16816(s8[nt], qh, kl);
            mma16816(s8[nt], ql, kh);
        }
        // + bias (L2) + mask (L2)
        {
            const float2* br0 = (const float2*)(g_bias + (size_t)(h * 64 + r0) * 64);
            const float2* br1 = (const float2*)(g_bias + (size_t)(h * 64 + r0 + 8) * 64);
            const float2* mr0 = (const float2*)(maskb + (size_t)r0 * 64);
            const float2* mr1 = (const float2*)(maskb + (size_t)(r0 + 8) * 64);
            int ci = lane & 3;
            #pragma unroll
            for (int nt = 0; nt < 8; nt++) {
                float2 bb = br0[nt * 4 + ci], mm = mr0[nt * 4 + ci];
                s8[nt][0] += bb.x + mm.x; s8[nt][1] += bb.y + mm.y;
                bb = br1[nt * 4 + ci]; mm = mr1[nt * 4 + ci];
                s8[nt][2] += bb.x + mm.x; s8[nt][3] += bb.y + mm.y;
            }
        }
        // softmax (register + shfl over lane%4 group)
        float mx0 = -1e30f, mx1 = -1e30f;
        #pragma unroll
        for (int nt = 0; nt < 8; nt++) {
            mx0 = fmaxf(mx0, fmaxf(s8[nt][0], s8[nt][1]));
            mx1 = fmaxf(mx1, fmaxf(s8[nt][2], s8[nt][3]));
        }
        mx0 = fmaxf(mx0, __shfl_xor_sync(0xffffffffu, mx0, 1));
        mx0 = fmaxf(mx0, __shfl_xor_sync(0xffffffffu, mx0, 2));
        mx1 = fmaxf(mx1, __shfl_xor_sync(0xffffffffu, mx1, 1));
        mx1 = fmaxf(mx1, __shfl_xor_sync(0xffffffffu, mx1, 2));
        float sum0 = 0.f, sum1 = 0.f;
        #pragma unroll
        for (int nt = 0; nt < 8; nt++) {
            s8[nt][0] = __expf(s8[nt][0] - mx0); sum0 += s8[nt][0];
            s8[nt][1] = __expf(s8[nt][1] - mx0); sum0 += s8[nt][1];
            s8[nt][2] = __expf(s8[nt][2] - mx1); sum1 += s8[nt][2];
            s8[nt][3] = __expf(s8[nt][3] - mx1); sum1 += s8[nt][3];
        }
        sum0 += __shfl_xor_sync(0xffffffffu, sum0, 1);
        sum0 += __shfl_xor_sync(0xffffffffu, sum0, 2);
        sum1 += __shfl_xor_sync(0xffffffffu, sum1, 1);
        sum1 += __shfl_xor_sync(0xffffffffu, sum1, 2);
        float inv0 = 1.f / sum0, inv1 = 1.f / sum1;
        #pragma unroll
        for (int nt = 0; nt < 8; nt++) {
            s8[nt][0] *= inv0; s8[nt][1] *= inv0;
            s8[nt][2] *= inv1; s8[nt][3] *= inv1;
        }
        // PV: O(16x16) = P(16x64) @ V(64x16), P fragments built in registers
        float o[2][4];
        o[0][0]=0.f;o[0][1]=0.f;o[0][2]=0.f;o[0][3]=0.f;
        o[1][0]=0.f;o[1][1]=0.f;o[1][2]=0.f;o[1][3]=0.f;
        #pragma unroll
        for (int kt = 0; kt < 4; kt++) {
            uint32_t pah[4], pal[4];
            split2(s8[2*kt][0],   s8[2*kt][1],   pah[0], pal[0]);
            split2(s8[2*kt][2],   s8[2*kt][3],   pah[1], pal[1]);
            split2(s8[2*kt+1][0], s8[2*kt+1][1], pah[2], pal[2]);
            split2(s8[2*kt+1][2], s8[2*kt+1][3], pah[3], pal[3]);
            #pragma unroll
            for (int nt2 = 0; nt2 < 2; nt2++) {
                uint32_t vr = (uint32_t)(128 + kt * 16 + (lane & 15)) * PITCHB
                            + (uint32_t)(h * 16 + nt2 * 8) * 2;
                uint32_t vh[2], vl[2];
                ldsm_x2t(vh, sb + QH_OFF + vr);
                ldsm_x2t(vl, sb + QL_OFF + vr);
                mma16816(o[nt2], pah, vh);
                mma16816(o[nt2], pah, vl);
                mma16816(o[nt2], pal, vh);
            }
        }
        // write O -> XH/XL (disjoint (row,col) region per unit)
        #pragma unroll
        for (int nt2 = 0; nt2 < 2; nt2++) {
            int c0 = h * 16 + nt2 * 8 + (lane & 3) * 2;
            uint32_t hp, lp;
            split2(o[nt2][0], o[nt2][1], hp, lp);
            uint32_t off = (uint32_t)r0 * PITCHB + c0 * 2;
            *(uint32_t*)(smc + XH_OFF + off) = hp;
            *(uint32_t*)(smc + XL_OFF + off) = lp;
            split2(o[nt2][2], o[nt2][3], hp, lp);
            off += 8 * PITCHB;
            *(uint32_t*)(smc + XH_OFF + off) = hp;
            *(uint32_t*)(smc + XL_OFF + off) = lp;
        }
    }
    __syncthreads();

    // ---- proj GEMM: (64x96)@(96x96) + b -> gmem; B fragments via LDG ----
    {
        float acc[4][4];
        #pragma unroll
        for (int j = 0; j < 4; j++)
            { acc[j][0] = 0.f; acc[j][1] = 0.f; acc[j][2] = 0.f; acc[j][3] = 0.f; }
        #pragma unroll
        for (int kt = 0; kt < 6; kt++) {
            uint32_t ah[4], al[4];
            uint32_t ar = (uint32_t)(mt * 16 + (lane & 15)) * PITCHB
                        + (uint32_t)(kt * 16 + ((lane >> 4) << 3)) * 2;
            ldsm_x4(ah, sb + XH_OFF + ar);
            ldsm_x4(al, sb + XL_OFF + ar);
            #pragma unroll
            for (int j = 0; j < 4; j++) {
                int nt = ng * 4 + j;
                int fi = ((kt * 12 + nt) * 2) * 32 + lane;
                uint2 bh = g_pwf[fi];
                uint2 bl = g_pwf[fi + 32];
                mma16816(acc[j], ah, (const uint32_t*)&bh);
                mma16816(acc[j], ah, (const uint32_t*)&bl);
                mma16816(acc[j], al, (const uint32_t*)&bh);
            }
        }
        float* ob = out + (size_t)b * 6144;
        const int r0 = mt * 16 + (lane >> 2);
        #pragma unroll
        for (int j = 0; j < 4; j++) {
            int c0 = (ng * 4 + j) * 8 + (lane & 3) * 2;
            float b0 = __ldg(proj_b + c0), b1 = __ldg(proj_b + c0 + 1);
            *(float2*)(ob + (size_t)r0 * 96 + c0) =
                make_float2(acc[j][0] + b0, acc[j][1] + b1);
            *(float2*)(ob + (size_t)(r0 + 8) * 96 + c0) =
                make_float2(acc[j][2] + b0, acc[j][3] + b1);
        }
    }
}

extern "C" void kernel_launch(void* const* d_in, const int* in_sizes, int n_in,
                              void* d_out, int out_size) {
    const float* x      = (const float*)d_in[0];
    const float* mask   = (const float*)d_in[1];
    const float* qkv_w  = (const float*)d_in[2];
    const float* qkv_b  = (const float*)d_in[3];
    const float* proj_w = (const float*)d_in[4];
    const float* proj_b = (const float*)d_in[5];
    const float* rpb    = (const float*)d_in[6];
    const int*   ridx   = (const int*)d_in[7];
    float* out = (float*)d_out;

    const int B_ = in_sizes[0] / (N_TOK * DIM);        // 8192
    const int nW = in_sizes[1] / (N_TOK * N_TOK);      // 512

    prep_kernel<<<168, 256>>>(qkv_w, proj_w, rpb, ridx);

    cudaFuncSetAttribute(win_attn_mma,
                         cudaFuncAttributeMaxDynamicSharedMemorySize, SMEM_BYTES);
    win_attn_mma<<<B_, THREADS, SMEM_BYTES>>>(x, mask, qkv_b, proj_b, out, nW);
}

// round 8
// speedup vs baseline: 3.9791x; 1.1948x over previous
#include <cuda_runtime.h>
#include <cuda_bf16.h>
#include <cstdint>

#define THREADS 256
#define N_TOK   64
#define DIM     96
#define HEADS   6

#define PITCHB  208u    // bytes per smem row (104 bf16; 13*16B, conflict-free LDSM)

// ---- smem byte offsets ----
#define XH_OFF   0u          // x / attn-out hi  [64][104]b16  = 13312
#define XL_OFF   13312u      // lo
#define QH_OFF   26624u      // q|k|v hi [192][104]           = 39936
#define QL_OFF   66560u
#define SMEM_BYTES 106496u   // <= 113.6KB -> 2 CTAs/SM

// ---- prepped globals: weights in mma B-fragment order ----
// g_qwf[(((s*6+kt)*12+nt)*2+plane)*32 + lane] = uint2{reg0, reg1}
__device__ uint2 g_qwf[13824];   // 3 slices * 6 kt * 12 nt * 2 planes * 32 lanes
__device__ uint2 g_pwf[4608];    // proj: 6 * 12 * 2 * 32
__device__ float g_bias[HEADS * 64 * 64]; // [h][n][m]

__device__ __forceinline__ void bsplit(float v, __nv_bfloat16& h, __nv_bfloat16& l) {
    h = __float2bfloat16_rn(v);
    l = __float2bfloat16_rn(v - __bfloat162float(h));
}
__device__ __forceinline__ uint32_t pack_plane(float a, float b, int p) {
    __nv_bfloat16 ah, al, bh, bl;
    bsplit(a, ah, al);
    bsplit(b, bh, bl);
    __nv_bfloat162 v;
    v.x = p ? al : ah;
    v.y = p ? bl : bh;
    return *reinterpret_cast<uint32_t*>(&v);
}

__global__ void __launch_bounds__(256)
prep_kernel(const float* __restrict__ qkv_w, const float* __restrict__ proj_w,
            const float* __restrict__ rpb, const int* __restrict__ ridx)
{
    int idx = blockIdx.x * 256 + threadIdx.x;
    if (idx < 13824) {
        int lane = idx & 31, p = (idx >> 5) & 1, nt = (idx >> 6) % 12;
        int kt = (idx / 768) % 6, s = idx / 4608;
        int nc = nt * 8 + (lane >> 2);
        int k0 = kt * 16 + (lane & 3) * 2;
        const float* wc = qkv_w + s * 96 + nc;
        uint2 r;
        r.x = pack_plane(wc[(k0)     * 288], wc[(k0 + 1) * 288], p);
        r.y = pack_plane(wc[(k0 + 8) * 288], wc[(k0 + 9) * 288], p);
        g_qwf[idx] = r;
    } else if (idx < 18432) {
        int j = idx - 13824;
        int lane = j & 31, p = (j >> 5) & 1, nt = (j >> 6) % 12, kt = j / 768;
        int nc = nt * 8 + (lane >> 2);
        int k0 = kt * 16 + (lane & 3) * 2;
        const float* wc = proj_w + nc;
        uint2 r;
        r.x = pack_plane(wc[(k0)     * 96], wc[(k0 + 1) * 96], p);
        r.y = pack_plane(wc[(k0 + 8) * 96], wc[(k0 + 9) * 96], p);
        g_pwf[j] = r;
    } else if (idx < 18432 + 24576) {
        int j = idx - 18432;
        int h = j >> 12, r = (j >> 6) & 63, m = j & 63;
        g_bias[j] = rpb[ridx[r * 64 + m] * HEADS + h];
    }
}

// ---- PTX helpers ----
__device__ __forceinline__ uint32_t smem_u32(const void* p) {
    uint32_t a;
    asm("{ .reg .u64 t; cvta.to.shared.u64 t, %1; cvt.u32.u64 %0, t; }" : "=r"(a) : "l"(p));
    return a;
}
__device__ __forceinline__ void ldsm_x4(uint32_t* r, uint32_t a) {
    asm volatile("ldmatrix.sync.aligned.m8n8.x4.shared.b16 {%0,%1,%2,%3}, [%4];"
        : "=r"(r[0]), "=r"(r[1]), "=r"(r[2]), "=r"(r[3]) : "r"(a));
}
__device__ __forceinline__ void ldsm_x2(uint32_t* r, uint32_t a) {
    asm volatile("ldmatrix.sync.aligned.m8n8.x2.shared.b16 {%0,%1}, [%2];"
        : "=r"(r[0]), "=r"(r[1]) : "r"(a));
}
__device__ __forceinline__ void ldsm_x2t(uint32_t* r, uint32_t a) {
    asm volatile("ldmatrix.sync.aligned.m8n8.x2.trans.shared.b16 {%0,%1}, [%2];"
        : "=r"(r[0]), "=r"(r[1]) : "r"(a));
}
__device__ __forceinline__ void mma16816(float* c, const uint32_t* a, const uint32_t* b) {
    asm volatile("mma.sync.aligned.m16n8k16.row.col.f32.bf16.bf16.f32 "
        "{%0,%1,%2,%3}, {%4,%5,%6,%7}, {%8,%9}, {%0,%1,%2,%3};"
        : "+f"(c[0]), "+f"(c[1]), "+f"(c[2]), "+f"(c[3])
        : "r"(a[0]), "r"(a[1]), "r"(a[2]), "r"(a[3]), "r"(b[0]), "r"(b[1]));
}
__device__ __forceinline__ void split2(float v0, float v1, uint32_t& hp, uint32_t& lp) {
    __nv_bfloat16 h0, l0, h1, l1;
    bsplit(v0, h0, l0);
    bsplit(v1, h1, l1);
    __nv_bfloat162 hh, ll;
    hh.x = h0; hh.y = h1; ll.x = l0; ll.y = l1;
    hp = *reinterpret_cast<uint32_t*>(&hh);
    lp = *reinterpret_cast<uint32_t*>(&ll);
}

extern __shared__ char smc[];

__global__ void __launch_bounds__(THREADS, 2)
win_attn_mma(const float* __restrict__ x,
             const float* __restrict__ mask,
             const float* __restrict__ qkv_b,
             const float* __restrict__ proj_b,
             float* __restrict__ out,
             int nW)
{
    const int t = threadIdx.x, wid = t >> 5, lane = t & 31, b = blockIdx.x;
    const uint32_t sb = smem_u32(smc);

    // ---- stage x (vectorized bf16 split) ----
    {
        const float4* xb4 = (const float4*)(x + (size_t)b * 6144);
        #pragma unroll
        for (int i = 0; i < 6; i++) {
            int e4 = t + i * THREADS;            // 1536 float4
            int r = e4 / 24, c4 = e4 % 24;       // 24 float4 per row
            float4 v = xb4[e4];
            uint32_t h0, l0, h1, l1;
            split2(v.x, v.y, h0, l0);
            split2(v.z, v.w, h1, l1);
            uint32_t off = (uint32_t)r * PITCHB + c4 * 8;
            *(uint32_t*)(smc + XH_OFF + off)     = h0;
            *(uint32_t*)(smc + XH_OFF + off + 4) = h1;
            *(uint32_t*)(smc + XL_OFF + off)     = l0;
            *(uint32_t*)(smc + XL_OFF + off + 4) = l1;
        }
    }
    __syncthreads();

    const int mt = wid & 3;      // m tile 0..3
    const int ng = wid >> 1 & 2; // unused placeholder (see below)
    const int g6 = wid >> 2;     // n group 0..1 (6 ntiles each)

    // ---- qkv GEMM: 3 slices of (64x96)@(96x96); B fragments via LDG ----
    #pragma unroll 1
    for (int s = 0; s < 3; s++) {
        float acc[6][4];
        #pragma unroll
        for (int j = 0; j < 6; j++)
            { acc[j][0] = 0.f; acc[j][1] = 0.f; acc[j][2] = 0.f; acc[j][3] = 0.f; }
        #pragma unroll
        for (int kt = 0; kt < 6; kt++) {
            uint32_t ah[4], al[4];
            uint32_t ar = (uint32_t)(mt * 16 + (lane & 15)) * PITCHB
                        + (uint32_t)(kt * 16 + ((lane >> 4) << 3)) * 2;
            ldsm_x4(ah, sb + XH_OFF + ar);
            ldsm_x4(al, sb + XL_OFF + ar);
            #pragma unroll
            for (int j = 0; j < 6; j++) {
                int nt = g6 * 6 + j;
                int fi = (((s * 6 + kt) * 12 + nt) * 2) * 32 + lane;
                uint2 bh = g_qwf[fi];
                uint2 bl = g_qwf[fi + 32];
                mma16816(acc[j], ah, (const uint32_t*)&bh);
                mma16816(acc[j], ah, (const uint32_t*)&bl);
                mma16816(acc[j], al, (const uint32_t*)&bh);
            }
        }
        // epilogue in registers (+bias, scale q, split) -> QKV region
        const float scl = (s == 0) ? 0.25f : 1.0f;
        const int r0 = mt * 16 + (lane >> 2);
        #pragma unroll
        for (int j = 0; j < 6; j++) {
            int c0 = (g6 * 6 + j) * 8 + (lane & 3) * 2;
            float b0 = __ldg(qkv_b + s * 96 + c0), b1 = __ldg(qkv_b + s * 96 + c0 + 1);
            uint32_t hp, lp;
            split2((acc[j][0] + b0) * scl, (acc[j][1] + b1) * scl, hp, lp);
            uint32_t off = (uint32_t)(s * 64 + r0) * PITCHB + c0 * 2;
            *(uint32_t*)(smc + QH_OFF + off) = hp;
            *(uint32_t*)(smc + QL_OFF + off) = lp;
            split2((acc[j][2] + b0) * scl, (acc[j][3] + b1) * scl, hp, lp);
            off += 8 * PITCHB;
            *(uint32_t*)(smc + QH_OFF + off) = hp;
            *(uint32_t*)(smc + QL_OFF + off) = lp;
        }
    }
    __syncthreads();   // QKV complete

    // ---- attention: 24 units (head, mtile), 3 per warp, all in registers ----
    const float* maskb = mask + (size_t)(b % nW) * 4096;
    #pragma unroll 1
    for (int iu = 0; iu < 3; iu++) {
        const int u = wid + 8 * iu;        // 0..23
        const int h = u >> 2, amt = u & 3;
        const int r0 = amt * 16 + (lane >> 2);

        uint32_t qh[4], ql[4];
        {
            uint32_t ar = (uint32_t)(amt * 16 + (lane & 15)) * PITCHB
                        + (uint32_t)(h * 16 + ((lane >> 4) << 3)) * 2;
            ldsm_x4(qh, sb + QH_OFF + ar);
            ldsm_x4(ql, sb + QL_OFF + ar);
        }
        float s8[8][4];
        #pragma unroll
        for (int nt = 0; nt < 8; nt++) {
            s8[nt][0] = 0.f; s8[nt][1] = 0.f; s8[nt][2] = 0.f; s8[nt][3] = 0.f;
            uint32_t br = (uint32_t)(64 + nt * 8 + (lane & 7)) * PITCHB
                        + (uint32_t)(h * 16 + ((lane >> 3) & 1) * 8) * 2;
            uint32_t kh[2], kl[2];
            ldsm_x2(kh, sb + QH_OFF + br);
            ldsm_x2(kl, sb + QL_OFF + br);
            mma16816(s8[nt], qh, kh);
            mma16816(s8[nt], qh, kl);
            mma16816(s8[nt], ql, kh);
        }
        // + bias (L2) + mask (L2)
        {
            const float2* br0 = (const float2*)(g_bias + (size_t)(h * 64 + r0) * 64);
            const float2* br1 = (const float2*)(g_bias + (size_t)(h * 64 + r0 + 8) * 64);
            const float2* mr0 = (const float2*)(maskb + (size_t)r0 * 64);
            const float2* mr1 = (const float2*)(maskb + (size_t)(r0 + 8) * 64);
            int ci = lane & 3;
            #pragma unroll
            for (int nt = 0; nt < 8; nt++) {
                float2 bb = br0[nt * 4 + ci], mm = mr0[nt * 4 + ci];
                s8[nt][0] += bb.x + mm.x; s8[nt][1] += bb.y + mm.y;
                bb = br1[nt * 4 + ci]; mm = mr1[nt * 4 + ci];
                s8[nt][2] += bb.x + mm.x; s8[nt][3] += bb.y + mm.y;
            }
        }
        // softmax (register + shfl over lane%4 group)
        float mx0 = -1e30f, mx1 = -1e30f;
        #pragma unroll
        for (int nt = 0; nt < 8; nt++) {
            mx0 = fmaxf(mx0, fmaxf(s8[nt][0], s8[nt][1]));
            mx1 = fmaxf(mx1, fmaxf(s8[nt][2], s8[nt][3]));
        }
        mx0 = fmaxf(mx0, __shfl_xor_sync(0xffffffffu, mx0, 1));
        mx0 = fmaxf(mx0, __shfl_xor_sync(0xffffffffu, mx0, 2));
        mx1 = fmaxf(mx1, __shfl_xor_sync(0xffffffffu, mx1, 1));
        mx1 = fmaxf(mx1, __shfl_xor_sync(0xffffffffu, mx1, 2));
        float sum0 = 0.f, sum1 = 0.f;
        #pragma unroll
        for (int nt = 0; nt < 8; nt++) {
            s8[nt][0] = __expf(s8[nt][0] - mx0); sum0 += s8[nt][0];
            s8[nt][1] = __expf(s8[nt][1] - mx0); sum0 += s8[nt][1];
            s8[nt][2] = __expf(s8[nt][2] - mx1); sum1 += s8[nt][2];
            s8[nt][3] = __expf(s8[nt][3] - mx1); sum1 += s8[nt][3];
        }
        sum0 += __shfl_xor_sync(0xffffffffu, sum0, 1);
        sum0 += __shfl_xor_sync(0xffffffffu, sum0, 2);
        sum1 += __shfl_xor_sync(0xffffffffu, sum1, 1);
        sum1 += __shfl_xor_sync(0xffffffffu, sum1, 2);
        float inv0 = 1.f / sum0, inv1 = 1.f / sum1;
        #pragma unroll
        for (int nt = 0; nt < 8; nt++) {
            s8[nt][0] *= inv0; s8[nt][1] *= inv0;
            s8[nt][2] *= inv1; s8[nt][3] *= inv1;
        }
        // PV: O(16x16) = P(16x64) @ V(64x16), P fragments built in registers
        float o[2][4];
        o[0][0]=0.f;o[0][1]=0.f;o[0][2]=0.f;o[0][3]=0.f;
        o[1][0]=0.f;o[1][1]=0.f;o[1][2]=0.f;o[1][3]=0.f;
        #pragma unroll
        for (int kt = 0; kt < 4; kt++) {
            uint32_t pah[4], pal[4];
            split2(s8[2*kt][0],   s8[2*kt][1],   pah[0], pal[0]);
            split2(s8[2*kt][2],   s8[2*kt][3],   pah[1], pal[1]);
            split2(s8[2*kt+1][0], s8[2*kt+1][1], pah[2], pal[2]);
            split2(s8[2*kt+1][2], s8[2*kt+1][3], pah[3], pal[3]);
            #pragma unroll
            for (int nt2 = 0; nt2 < 2; nt2++) {
                uint32_t vr = (uint32_t)(128 + kt * 16 + (lane & 15)) * PITCHB
                            + (uint32_t)(h * 16 + nt2 * 8) * 2;
                uint32_t vh[2], vl[2];
                ldsm_x2t(vh, sb + QH_OFF + vr);
                ldsm_x2t(vl, sb + QL_OFF + vr);
                mma16816(o[nt2], pah, vh);
                mma16816(o[nt2], pah, vl);
                mma16816(o[nt2], pal, vh);
            }
        }
        // write O -> XH/XL (disjoint (row,col) region per unit)
        #pragma unroll
        for (int nt2 = 0; nt2 < 2; nt2++) {
            int c0 = h * 16 + nt2 * 8 + (lane & 3) * 2;
            uint32_t hp, lp;
            split2(o[nt2][0], o[nt2][1], hp, lp);
            uint32_t off = (uint32_t)r0 * PITCHB + c0 * 2;
            *(uint32_t*)(smc + XH_OFF + off) = hp;
            *(uint32_t*)(smc + XL_OFF + off) = lp;
            split2(o[nt2][2], o[nt2][3], hp, lp);
            off += 8 * PITCHB;
            *(uint32_t*)(smc + XH_OFF + off) = hp;
            *(uint32_t*)(smc + XL_OFF + off) = lp;
        }
    }
    __syncthreads();

    // ---- proj GEMM: (64x96)@(96x96) + b -> gmem; B fragments via LDG ----
    {
        float acc[6][4];
        #pragma unroll
        for (int j = 0; j < 6; j++)
            { acc[j][0] = 0.f; acc[j][1] = 0.f; acc[j][2] = 0.f; acc[j][3] = 0.f; }
        #pragma unroll
        for (int kt = 0; kt < 6; kt++) {
            uint32_t ah[4], al[4];
            uint32_t ar = (uint32_t)(mt * 16 + (lane & 15)) * PITCHB
                        + (uint32_t)(kt * 16 + ((lane >> 4) << 3)) * 2;
            ldsm_x4(ah, sb + XH_OFF + ar);
            ldsm_x4(al, sb + XL_OFF + ar);
            #pragma unroll
            for (int j = 0; j < 6; j++) {
                int nt = g6 * 6 + j;
                int fi = ((kt * 12 + nt) * 2) * 32 + lane;
                uint2 bh = g_pwf[fi];
                uint2 bl = g_pwf[fi + 32];
                mma16816(acc[j], ah, (const uint32_t*)&bh);
                mma16816(acc[j], ah, (const uint32_t*)&bl);
                mma16816(acc[j], al, (const uint32_t*)&bh);
            }
        }
        float* ob = out + (size_t)b * 6144;
        const int r0 = mt * 16 + (lane >> 2);
        #pragma unroll
        for (int j = 0; j < 6; j++) {
            int c0 = (g6 * 6 + j) * 8 + (lane & 3) * 2;
            float b0 = __ldg(proj_b + c0), b1 = __ldg(proj_b + c0 + 1);
            *(float2*)(ob + (size_t)r0 * 96 + c0) =
                make_float2(acc[j][0] + b0, acc[j][1] + b1);
            *(float2*)(ob + (size_t)(r0 + 8) * 96 + c0) =
                make_float2(acc[j][2] + b0, acc[j][3] + b1);
        }
    }
}

extern "C" void kernel_launch(void* const* d_in, const int* in_sizes, int n_in,
                              void* d_out, int out_size) {
    const float* x      = (const float*)d_in[0];
    const float* mask   = (const float*)d_in[1];
    const float* qkv_w  = (const float*)d_in[2];
    const float* qkv_b  = (const float*)d_in[3];
    const float* proj_w = (const float*)d_in[4];
    const float* proj_b = (const float*)d_in[5];
    const float* rpb    = (const float*)d_in[6];
    const int*   ridx   = (const int*)d_in[7];
    float* out = (float*)d_out;

    const int B_ = in_sizes[0] / (N_TOK * DIM);        // 8192
    const int nW = in_sizes[1] / (N_TOK * N_TOK);      // 512

    prep_kernel<<<168, 256>>>(qkv_w, proj_w, rpb, ridx);

    cudaFuncSetAttribute(win_attn_mma,
                         cudaFuncAttributeMaxDynamicSharedMemorySize, SMEM_BYTES);
    win_attn_mma<<<B_, THREADS, SMEM_BYTES>>>(x, mask, qkv_b, proj_b, out, nW);
}

// round 9
// speedup vs baseline: 3.9954x; 1.0041x over previous
#include <cuda_runtime.h>
#include <cuda_bf16.h>
#include <cstdint>

#define THREADS 256
#define N_TOK   64
#define DIM     96
#define HEADS   6

#define PITCHB  208u    // bytes per smem row (104 bf16; 13*16B, conflict-free LDSM)

// ---- smem: only q|k|v hi/lo [192][104]b16 (q rows become O in-place) ----
#define QH_OFF   0u
#define QL_OFF   39936u
#define SMEM_BYTES 79872u   // 2 CTAs/SM, large L1D carveout remains

// ---- prepped globals: weights in mma B-fragment order ----
__device__ uint2 g_qwf[13824];   // 3 slices * 6 kt * 12 nt * 2 planes * 32 lanes
__device__ uint2 g_pwf[4608];    // proj: 6 * 12 * 2 * 32
__device__ float g_bias[HEADS * 64 * 64]; // [h][n][m]

__device__ __forceinline__ void bsplit(float v, __nv_bfloat16& h, __nv_bfloat16& l) {
    h = __float2bfloat16_rn(v);
    l = __float2bfloat16_rn(v - __bfloat162float(h));
}
__device__ __forceinline__ uint32_t pack_plane(float a, float b, int p) {
    __nv_bfloat16 ah, al, bh, bl;
    bsplit(a, ah, al);
    bsplit(b, bh, bl);
    __nv_bfloat162 v;
    v.x = p ? al : ah;
    v.y = p ? bl : bh;
    return *reinterpret_cast<uint32_t*>(&v);
}

__global__ void __launch_bounds__(256)
prep_kernel(const float* __restrict__ qkv_w, const float* __restrict__ proj_w,
            const float* __restrict__ rpb, const int* __restrict__ ridx)
{
    int idx = blockIdx.x * 256 + threadIdx.x;
    if (idx < 13824) {
        int lane = idx & 31, p = (idx >> 5) & 1, nt = (idx >> 6) % 12;
        int kt = (idx / 768) % 6, s = idx / 4608;
        int nc = nt * 8 + (lane >> 2);
        int k0 = kt * 16 + (lane & 3) * 2;
        const float* wc = qkv_w + s * 96 + nc;
        uint2 r;
        r.x = pack_plane(wc[(k0)     * 288], wc[(k0 + 1) * 288], p);
        r.y = pack_plane(wc[(k0 + 8) * 288], wc[(k0 + 9) * 288], p);
        g_qwf[idx] = r;
    } else if (idx < 18432) {
        int j = idx - 13824;
        int lane = j & 31, p = (j >> 5) & 1, nt = (j >> 6) % 12, kt = j / 768;
        int nc = nt * 8 + (lane >> 2);
        int k0 = kt * 16 + (lane & 3) * 2;
        const float* wc = proj_w + nc;
        uint2 r;
        r.x = pack_plane(wc[(k0)     * 96], wc[(k0 + 1) * 96], p);
        r.y = pack_plane(wc[(k0 + 8) * 96], wc[(k0 + 9) * 96], p);
        g_pwf[j] = r;
    } else if (idx < 18432 + 24576) {
        int j = idx - 18432;
        int h = j >> 12, r = (j >> 6) & 63, m = j & 63;
        g_bias[j] = rpb[ridx[r * 64 + m] * HEADS + h];
    }
}

// ---- PTX helpers ----
__device__ __forceinline__ uint32_t smem_u32(const void* p) {
    uint32_t a;
    asm("{ .reg .u64 t; cvta.to.shared.u64 t, %1; cvt.u32.u64 %0, t; }" : "=r"(a) : "l"(p));
    return a;
}
__device__ __forceinline__ void ldsm_x4(uint32_t* r, uint32_t a) {
    asm volatile("ldmatrix.sync.aligned.m8n8.x4.shared.b16 {%0,%1,%2,%3}, [%4];"
        : "=r"(r[0]), "=r"(r[1]), "=r"(r[2]), "=r"(r[3]) : "r"(a));
}
__device__ __forceinline__ void ldsm_x4t(uint32_t* r, uint32_t a) {
    asm volatile("ldmatrix.sync.aligned.m8n8.x4.trans.shared.b16 {%0,%1,%2,%3}, [%4];"
        : "=r"(r[0]), "=r"(r[1]), "=r"(r[2]), "=r"(r[3]) : "r"(a));
}
__device__ __forceinline__ void mma16816(float* c, const uint32_t* a, const uint32_t* b) {
    asm volatile("mma.sync.aligned.m16n8k16.row.col.f32.bf16.bf16.f32 "
        "{%0,%1,%2,%3}, {%4,%5,%6,%7}, {%8,%9}, {%0,%1,%2,%3};"
        : "+f"(c[0]), "+f"(c[1]), "+f"(c[2]), "+f"(c[3])
        : "r"(a[0]), "r"(a[1]), "r"(a[2]), "r"(a[3]), "r"(b[0]), "r"(b[1]));
}
__device__ __forceinline__ void mma16816_b(float* c, const uint32_t* a,
                                           uint32_t b0, uint32_t b1) {
    asm volatile("mma.sync.aligned.m16n8k16.row.col.f32.bf16.bf16.f32 "
        "{%0,%1,%2,%3}, {%4,%5,%6,%7}, {%8,%9}, {%0,%1,%2,%3};"
        : "+f"(c[0]), "+f"(c[1]), "+f"(c[2]), "+f"(c[3])
        : "r"(a[0]), "r"(a[1]), "r"(a[2]), "r"(a[3]), "r"(b0), "r"(b1));
}
__device__ __forceinline__ void split2(float v0, float v1, uint32_t& hp, uint32_t& lp) {
    __nv_bfloat16 h0, l0, h1, l1;
    bsplit(v0, h0, l0);
    bsplit(v1, h1, l1);
    __nv_bfloat162 hh, ll;
    hh.x = h0; hh.y = h1; ll.x = l0; ll.y = l1;
    hp = *reinterpret_cast<uint32_t*>(&hh);
    lp = *reinterpret_cast<uint32_t*>(&ll);
}

extern __shared__ char smc[];

__global__ void __launch_bounds__(THREADS, 2)
win_attn_mma(const float* __restrict__ x,
             const float* __restrict__ mask,
             const float* __restrict__ qkv_b,
             const float* __restrict__ proj_b,
             float* __restrict__ out,
             int nW)
{
    const int t = threadIdx.x, wid = t >> 5, lane = t & 31, b = blockIdx.x;
    const uint32_t sb = smem_u32(smc);
    const int mt = wid & 3;      // m tile 0..3
    const int g6 = wid >> 2;     // n group 0..1

    // ---- load A fragments (x) directly from gmem, split once, hold for 3 slices ----
    uint32_t xah[6][4], xal[6][4];
    {
        const float* xb = x + (size_t)b * 6144;
        const int gr = lane >> 2, ck = (lane & 3) * 2;
        const float* base = xb + (size_t)(mt * 16 + gr) * 96 + ck;
        #pragma unroll
        for (int kt = 0; kt < 6; kt++) {
            float2 v00 = *(const float2*)(base + kt * 16);
            float2 v10 = *(const float2*)(base + kt * 16 + 8 * 96);
            float2 v01 = *(const float2*)(base + kt * 16 + 8);
            float2 v11 = *(const float2*)(base + kt * 16 + 8 * 96 + 8);
            split2(v00.x, v00.y, xah[kt][0], xal[kt][0]);
            split2(v10.x, v10.y, xah[kt][1], xal[kt][1]);
            split2(v01.x, v01.y, xah[kt][2], xal[kt][2]);
            split2(v11.x, v11.y, xah[kt][3], xal[kt][3]);
        }
    }

    // ---- qkv GEMM: 3 slices of (64x96)@(96x96); B fragments via LDG ----
    #pragma unroll 1
    for (int s = 0; s < 3; s++) {
        float acc[6][4];
        #pragma unroll
        for (int j = 0; j < 6; j++)
            { acc[j][0] = 0.f; acc[j][1] = 0.f; acc[j][2] = 0.f; acc[j][3] = 0.f; }
        #pragma unroll
        for (int kt = 0; kt < 6; kt++) {
            #pragma unroll
            for (int j = 0; j < 6; j++) {
                int nt = g6 * 6 + j;
                int fi = (((s * 6 + kt) * 12 + nt) * 2) * 32 + lane;
                uint2 bh = g_qwf[fi];
                uint2 bl = g_qwf[fi + 32];
                mma16816(acc[j], xah[kt], (const uint32_t*)&bh);
                mma16816(acc[j], xah[kt], (const uint32_t*)&bl);
                mma16816(acc[j], xal[kt], (const uint32_t*)&bh);
            }
        }
        // epilogue in registers (+bias, scale q, split) -> QKV region
        const float scl = (s == 0) ? 0.25f : 1.0f;
        const int r0 = mt * 16 + (lane >> 2);
        #pragma unroll
        for (int j = 0; j < 6; j++) {
            int c0 = (g6 * 6 + j) * 8 + (lane & 3) * 2;
            float b0 = __ldg(qkv_b + s * 96 + c0), b1 = __ldg(qkv_b + s * 96 + c0 + 1);
            uint32_t hp, lp;
            split2((acc[j][0] + b0) * scl, (acc[j][1] + b1) * scl, hp, lp);
            uint32_t off = (uint32_t)(s * 64 + r0) * PITCHB + c0 * 2;
            *(uint32_t*)(smc + QH_OFF + off) = hp;
            *(uint32_t*)(smc + QL_OFF + off) = lp;
            split2((acc[j][2] + b0) * scl, (acc[j][3] + b1) * scl, hp, lp);
            off += 8 * PITCHB;
            *(uint32_t*)(smc + QH_OFF + off) = hp;
            *(uint32_t*)(smc + QL_OFF + off) = lp;
        }
    }
    __syncthreads();   // QKV complete

    // ---- attention: unit (h,amt) <-> (wid,iu) bijective; amt == mt for this warp ----
    const float* maskb = mask + (size_t)(b % nW) * 4096;
    uint32_t oah[3][4], oal[3][4];   // own O tiles in proj-A fragment form
    #pragma unroll 1
    for (int iu = 0; iu < 3; iu++) {
        const int h = g6 + 2 * iu;     // head
        const int r0 = mt * 16 + (lane >> 2);

        uint32_t qh[4], ql[4];
        {
            uint32_t ar = (uint32_t)(mt * 16 + (lane & 15)) * PITCHB
                        + (uint32_t)(h * 16 + ((lane >> 4) << 3)) * 2;
            ldsm_x4(qh, sb + QH_OFF + ar);
            ldsm_x4(ql, sb + QL_OFF + ar);
        }
        float s8[8][4];
        #pragma unroll
        for (int ntp = 0; ntp < 4; ntp++) {
            uint32_t kh[4], kl[4];
            uint32_t br = (uint32_t)(64 + ntp * 16 + (lane & 15)) * PITCHB
                        + (uint32_t)(h * 16 + ((lane >> 4) << 3)) * 2;
            ldsm_x4(kh, sb + QH_OFF + br);
            ldsm_x4(kl, sb + QL_OFF + br);
            #pragma unroll
            for (int half = 0; half < 2; half++) {
                int nt = 2 * ntp + half;
                s8[nt][0] = 0.f; s8[nt][1] = 0.f; s8[nt][2] = 0.f; s8[nt][3] = 0.f;
                mma16816_b(s8[nt], qh, kh[half], kh[half + 2]);
                mma16816_b(s8[nt], qh, kl[half], kl[half + 2]);
                mma16816_b(s8[nt], ql, kh[half], kh[half + 2]);
            }
        }
        // + bias (L2) + mask (L2)
        {
            const float2* br0 = (const float2*)(g_bias + (size_t)(h * 64 + r0) * 64);
            const float2* br1 = (const float2*)(g_bias + (size_t)(h * 64 + r0 + 8) * 64);
            const float2* mr0 = (const float2*)(maskb + (size_t)r0 * 64);
            const float2* mr1 = (const float2*)(maskb + (size_t)(r0 + 8) * 64);
            int ci = lane & 3;
            #pragma unroll
            for (int nt = 0; nt < 8; nt++) {
                float2 bb = br0[nt * 4 + ci], mm = mr0[nt * 4 + ci];
                s8[nt][0] += bb.x + mm.x; s8[nt][1] += bb.y + mm.y;
                bb = br1[nt * 4 + ci]; mm = mr1[nt * 4 + ci];
                s8[nt][2] += bb.x + mm.x; s8[nt][3] += bb.y + mm.y;
            }
        }
        // softmax (register + shfl over lane%4 group)
        float mx0 = -1e30f, mx1 = -1e30f;
        #pragma unroll
        for (int nt = 0; nt < 8; nt++) {
            mx0 = fmaxf(mx0, fmaxf(s8[nt][0], s8[nt][1]));
            mx1 = fmaxf(mx1, fmaxf(s8[nt][2], s8[nt][3]));
        }
        mx0 = fmaxf(mx0, __shfl_xor_sync(0xffffffffu, mx0, 1));
        mx0 = fmaxf(mx0, __shfl_xor_sync(0xffffffffu, mx0, 2));
        mx1 = fmaxf(mx1, __shfl_xor_sync(0xffffffffu, mx1, 1));
        mx1 = fmaxf(mx1, __shfl_xor_sync(0xffffffffu, mx1, 2));
        float sum0 = 0.f, sum1 = 0.f;
        #pragma unroll
        for (int nt = 0; nt < 8; nt++) {
            s8[nt][0] = __expf(s8[nt][0] - mx0); sum0 += s8[nt][0];
            s8[nt][1] = __expf(s8[nt][1] - mx0); sum0 += s8[nt][1];
            s8[nt][2] = __expf(s8[nt][2] - mx1); sum1 += s8[nt][2];
            s8[nt][3] = __expf(s8[nt][3] - mx1); sum1 += s8[nt][3];
        }
        sum0 += __shfl_xor_sync(0xffffffffu, sum0, 1);
        sum0 += __shfl_xor_sync(0xffffffffu, sum0, 2);
        sum1 += __shfl_xor_sync(0xffffffffu, sum1, 1);
        sum1 += __shfl_xor_sync(0xffffffffu, sum1, 2);
        float inv0 = 1.f / sum0, inv1 = 1.f / sum1;
        #pragma unroll
        for (int nt = 0; nt < 8; nt++) {
            s8[nt][0] *= inv0; s8[nt][1] *= inv0;
            s8[nt][2] *= inv1; s8[nt][3] *= inv1;
        }
        // PV: O(16x16) = P(16x64) @ V(64x16)
        float o[2][4];
        o[0][0]=0.f;o[0][1]=0.f;o[0][2]=0.f;o[0][3]=0.f;
        o[1][0]=0.f;o[1][1]=0.f;o[1][2]=0.f;o[1][3]=0.f;
        #pragma unroll
        for (int kt = 0; kt < 4; kt++) {
            uint32_t pah[4], pal[4];
            split2(s8[2*kt][0],   s8[2*kt][1],   pah[0], pal[0]);
            split2(s8[2*kt][2],   s8[2*kt][3],   pah[1], pal[1]);
            split2(s8[2*kt+1][0], s8[2*kt+1][1], pah[2], pal[2]);
            split2(s8[2*kt+1][2], s8[2*kt+1][3], pah[3], pal[3]);
            uint32_t vr = (uint32_t)(128 + kt * 16 + (lane & 15)) * PITCHB
                        + (uint32_t)(h * 16 + ((lane >> 4) << 3)) * 2;
            uint32_t vh[4], vl[4];
            ldsm_x4t(vh, sb + QH_OFF + vr);
            ldsm_x4t(vl, sb + QL_OFF + vr);
            #pragma unroll
            for (int nt2 = 0; nt2 < 2; nt2++) {
                mma16816_b(o[nt2], pah, vh[nt2*2], vh[nt2*2+1]);
                mma16816_b(o[nt2], pah, vl[nt2*2], vl[nt2*2+1]);
                mma16816_b(o[nt2], pal, vh[nt2*2], vh[nt2*2+1]);
            }
        }
        // split O; keep in regs (proj A frag) AND write into dead q rows for partner
        #pragma unroll
        for (int nt2 = 0; nt2 < 2; nt2++) {
            int c0 = h * 16 + nt2 * 8 + (lane & 3) * 2;
            uint32_t hp0, lp0, hp1, lp1;
            split2(o[nt2][0], o[nt2][1], hp0, lp0);
            split2(o[nt2][2], o[nt2][3], hp1, lp1);
            oah[iu][nt2*2]   = hp0; oal[iu][nt2*2]   = lp0;
            oah[iu][nt2*2+1] = hp1; oal[iu][nt2*2+1] = lp1;
            uint32_t off = (uint32_t)r0 * PITCHB + c0 * 2;
            *(uint32_t*)(smc + QH_OFF + off) = hp0;
            *(uint32_t*)(smc + QL_OFF + off) = lp0;
            off += 8 * PITCHB;
            *(uint32_t*)(smc + QH_OFF + off) = hp1;
            *(uint32_t*)(smc + QL_OFF + off) = lp1;
        }
    }
    __syncthreads();   // O complete (rows 0-63 of QKV region)

    // ---- proj GEMM: A = O (own tiles in regs, partner's via ldsm); B via LDG ----
    {
        float acc[6][4];
        #pragma unroll
        for (int j = 0; j < 6; j++)
            { acc[j][0] = 0.f; acc[j][1] = 0.f; acc[j][2] = 0.f; acc[j][3] = 0.f; }
        #pragma unroll
        for (int kt = 0; kt < 6; kt++) {
            uint32_t ah[4], al[4];
            if ((kt & 1) == g6) {
                int iu = kt >> 1;
                ah[0] = oah[iu][0]; ah[1] = oah[iu][1]; ah[2] = oah[iu][2]; ah[3] = oah[iu][3];
                al[0] = oal[iu][0]; al[1] = oal[iu][1]; al[2] = oal[iu][2]; al[3] = oal[iu][3];
            } else {
                uint32_t ar = (uint32_t)(mt * 16 + (lane & 15)) * PITCHB
                            + (uint32_t)(kt * 16 + ((lane >> 4) << 3)) * 2;
                ldsm_x4(ah, sb + QH_OFF + ar);
                ldsm_x4(al, sb + QL_OFF + ar);
            }
            #pragma unroll
            for (int j = 0; j < 6; j++) {
                int nt = g6 * 6 + j;
                int fi = ((kt * 12 + nt) * 2) * 32 + lane;
                uint2 bh = g_pwf[fi];
                uint2 bl = g_pwf[fi + 32];
                mma16816(acc[j], ah, (const uint32_t*)&bh);
                mma16816(acc[j], ah, (const uint32_t*)&bl);
                mma16816(acc[j], al, (const uint32_t*)&bh);
            }
        }
        float* ob = out + (size_t)b * 6144;
        const int r0 = mt * 16 + (lane >> 2);
        #pragma unroll
        for (int j = 0; j < 6; j++) {
            int c0 = (g6 * 6 + j) * 8 + (lane & 3) * 2;
            float b0 = __ldg(proj_b + c0), b1 = __ldg(proj_b + c0 + 1);
            *(float2*)(ob + (size_t)r0 * 96 + c0) =
                make_float2(acc[j][0] + b0, acc[j][1] + b1);
            *(float2*)(ob + (size_t)(r0 + 8) * 96 + c0) =
                make_float2(acc[j][2] + b0, acc[j][3] + b1);
        }
    }
}

extern "C" void kernel_launch(void* const* d_in, const int* in_sizes, int n_in,
                              void* d_out, int out_size) {
    const float* x      = (const float*)d_in[0];
    const float* mask   = (const float*)d_in[1];
    const float* qkv_w  = (const float*)d_in[2];
    const float* qkv_b  = (const float*)d_in[3];
    const float* proj_w = (const float*)d_in[4];
    const float* proj_b = (const float*)d_in[5];
    const float* rpb    = (const float*)d_in[6];
    const int*   ridx   = (const int*)d_in[7];
    float* out = (float*)d_out;

    const int B_ = in_sizes[0] / (N_TOK * DIM);        // 8192
    const int nW = in_sizes[1] / (N_TOK * N_TOK);      // 512

    prep_kernel<<<168, 256>>>(qkv_w, proj_w, rpb, ridx);

    cudaFuncSetAttribute(win_attn_mma,
                         cudaFuncAttributeMaxDynamicSharedMemorySize, SMEM_BYTES);
    win_attn_mma<<<B_, THREADS, SMEM_BYTES>>>(x, mask, qkv_b, proj_b, out, nW);
}

// round 10
// speedup vs baseline: 4.9200x; 1.2314x over previous
#include <cuda_runtime.h>
#include <cuda_fp16.h>
#include <cstdint>

#define THREADS 256
#define N_TOK   64
#define DIM     96
#define HEADS   6

#define PITCHB  208u    // bytes per smem row (104 fp16; 13*16B, conflict-free LDSM)

// ---- smem planes: q hi, q lo, k, v  (q planes become O hi/lo in-place) ----
#define QH_OFF   0u
#define QL_OFF   13312u
#define KP_OFF   26624u
#define VP_OFF   39936u
#define SMEM_BYTES 53248u   // 2 CTAs/SM, ~175KB L1D carveout remains

// ---- prepped globals: weights in mma B-fragment order (single fp16 plane) ----
// uint4 = {nt0.reg0, nt0.reg1, nt1.reg0, nt1.reg1} for an nt-pair
__device__ uint4  g_qwf4[3456];   // 3 slices * 6 kt * 6 np * 32 lanes
__device__ uint4  g_pwf4[1152];   // 6 kt * 6 np * 32 lanes
__device__ __half g_biash[HEADS * 64 * 64]; // [h][n][m] fp16

__device__ __forceinline__ uint32_t packh(float a, float b) {
    __half2 v;
    v.x = __float2half_rn(a);
    v.y = __float2half_rn(b);
    return *reinterpret_cast<uint32_t*>(&v);
}
__device__ __forceinline__ void split2h(float v0, float v1, uint32_t& hp, uint32_t& lp) {
    __half h0 = __float2half_rn(v0), h1 = __float2half_rn(v1);
    __half l0 = __float2half_rn(v0 - __half2float(h0));
    __half l1 = __float2half_rn(v1 - __half2float(h1));
    __half2 hh, ll;
    hh.x = h0; hh.y = h1; ll.x = l0; ll.y = l1;
    hp = *reinterpret_cast<uint32_t*>(&hh);
    lp = *reinterpret_cast<uint32_t*>(&ll);
}

__global__ void __launch_bounds__(256)
prep_kernel(const float* __restrict__ qkv_w, const float* __restrict__ proj_w,
            const float* __restrict__ rpb, const int* __restrict__ ridx)
{
    int idx = blockIdx.x * 256 + threadIdx.x;
    if (idx < 3456) {
        int lane = idx & 31, np = (idx >> 5) % 6, kt = (idx / 192) % 6, s = idx / 1152;
        int k0 = kt * 16 + (lane & 3) * 2;
        int nc0 = (2 * np) * 8 + (lane >> 2);
        int nc1 = nc0 + 8;
        const float* w0 = qkv_w + s * 96 + nc0;
        const float* w1 = qkv_w + s * 96 + nc1;
        uint4 r;
        r.x = packh(w0[(k0)     * 288], w0[(k0 + 1) * 288]);
        r.y = packh(w0[(k0 + 8) * 288], w0[(k0 + 9) * 288]);
        r.z = packh(w1[(k0)     * 288], w1[(k0 + 1) * 288]);
        r.w = packh(w1[(k0 + 8) * 288], w1[(k0 + 9) * 288]);
        g_qwf4[idx] = r;
    } else if (idx < 4608) {
        int j = idx - 3456;
        int lane = j & 31, np = (j >> 5) % 6, kt = j / 192;
        int k0 = kt * 16 + (lane & 3) * 2;
        int nc0 = (2 * np) * 8 + (lane >> 2);
        int nc1 = nc0 + 8;
        const float* w0 = proj_w + nc0;
        const float* w1 = proj_w + nc1;
        uint4 r;
        r.x = packh(w0[(k0)     * 96], w0[(k0 + 1) * 96]);
        r.y = packh(w0[(k0 + 8) * 96], w0[(k0 + 9) * 96]);
        r.z = packh(w1[(k0)     * 96], w1[(k0 + 1) * 96]);
        r.w = packh(w1[(k0 + 8) * 96], w1[(k0 + 9) * 96]);
        g_pwf4[j] = r;
    } else if (idx < 4608 + 24576) {
        int j = idx - 4608;
        int h = j >> 12, r = (j >> 6) & 63, m = j & 63;
        g_biash[j] = __float2half_rn(rpb[ridx[r * 64 + m] * HEADS + h]);
    }
}

// ---- PTX helpers ----
__device__ __forceinline__ uint32_t smem_u32(const void* p) {
    uint32_t a;
    asm("{ .reg .u64 t; cvta.to.shared.u64 t, %1; cvt.u32.u64 %0, t; }" : "=r"(a) : "l"(p));
    return a;
}
__device__ __forceinline__ void ldsm_x4(uint32_t* r, uint32_t a) {
    asm volatile("ldmatrix.sync.aligned.m8n8.x4.shared.b16 {%0,%1,%2,%3}, [%4];"
        : "=r"(r[0]), "=r"(r[1]), "=r"(r[2]), "=r"(r[3]) : "r"(a));
}
__device__ __forceinline__ void ldsm_x4t(uint32_t* r, uint32_t a) {
    asm volatile("ldmatrix.sync.aligned.m8n8.x4.trans.shared.b16 {%0,%1,%2,%3}, [%4];"
        : "=r"(r[0]), "=r"(r[1]), "=r"(r[2]), "=r"(r[3]) : "r"(a));
}
__device__ __forceinline__ void mma_h(float* c, const uint32_t* a,
                                      uint32_t b0, uint32_t b1) {
    asm volatile("mma.sync.aligned.m16n8k16.row.col.f32.f16.f16.f32 "
        "{%0,%1,%2,%3}, {%4,%5,%6,%7}, {%8,%9}, {%0,%1,%2,%3};"
        : "+f"(c[0]), "+f"(c[1]), "+f"(c[2]), "+f"(c[3])
        : "r"(a[0]), "r"(a[1]), "r"(a[2]), "r"(a[3]), "r"(b0), "r"(b1));
}

extern __shared__ char smc[];

__global__ void __launch_bounds__(THREADS, 2)
win_attn_mma(const float* __restrict__ x,
             const float* __restrict__ mask,
             const float* __restrict__ qkv_b,
             const float* __restrict__ proj_b,
             float* __restrict__ out,
             int nW)
{
    const int t = threadIdx.x, wid = t >> 5, lane = t & 31, b = blockIdx.x;
    const uint32_t sb = smem_u32(smc);
    const int mt = wid & 3;      // m tile 0..3
    const int g6 = wid >> 2;     // n group 0..1

    // ---- load A fragments (x) from gmem, fp16 split, hold for all 3 slices ----
    uint32_t xah[6][4], xal[6][4];
    {
        const float* xb = x + (size_t)b * 6144;
        const int gr = lane >> 2, ck = (lane & 3) * 2;
        const float* base = xb + (size_t)(mt * 16 + gr) * 96 + ck;
        #pragma unroll
        for (int kt = 0; kt < 6; kt++) {
            float2 v00 = *(const float2*)(base + kt * 16);
            float2 v10 = *(const float2*)(base + kt * 16 + 8 * 96);
            float2 v01 = *(const float2*)(base + kt * 16 + 8);
            float2 v11 = *(const float2*)(base + kt * 16 + 8 * 96 + 8);
            split2h(v00.x, v00.y, xah[kt][0], xal[kt][0]);
            split2h(v10.x, v10.y, xah[kt][1], xal[kt][1]);
            split2h(v01.x, v01.y, xah[kt][2], xal[kt][2]);
            split2h(v11.x, v11.y, xah[kt][3], xal[kt][3]);
        }
    }

    // ---- qkv GEMM: 3 slices; A hi/lo fp16, B single fp16 (uint4 nt-pairs) ----
    #pragma unroll 1
    for (int s = 0; s < 3; s++) {
        float acc[6][4];
        #pragma unroll
        for (int j = 0; j < 6; j++)
            { acc[j][0] = 0.f; acc[j][1] = 0.f; acc[j][2] = 0.f; acc[j][3] = 0.f; }
        #pragma unroll
        for (int kt = 0; kt < 6; kt++) {
            #pragma unroll
            for (int jp = 0; jp < 3; jp++) {
                int fi = ((s * 6 + kt) * 6 + g6 * 3 + jp) * 32 + lane;
                uint4 w = g_qwf4[fi];
                mma_h(acc[2*jp],   xah[kt], w.x, w.y);
                mma_h(acc[2*jp],   xal[kt], w.x, w.y);
                mma_h(acc[2*jp+1], xah[kt], w.z, w.w);
                mma_h(acc[2*jp+1], xal[kt], w.z, w.w);
            }
        }
        // epilogue: +bias; q: *0.25, split hi/lo -> QH/QL; k/v: single fp16 plane
        const int r0 = mt * 16 + (lane >> 2);
        #pragma unroll
        for (int j = 0; j < 6; j++) {
            int c0 = (g6 * 6 + j) * 8 + (lane & 3) * 2;
            float b0 = __ldg(qkv_b + s * 96 + c0), b1 = __ldg(qkv_b + s * 96 + c0 + 1);
            float v0 = acc[j][0] + b0, v1 = acc[j][1] + b1;
            float v2 = acc[j][2] + b0, v3 = acc[j][3] + b1;
            uint32_t off = (uint32_t)r0 * PITCHB + c0 * 2;
            if (s == 0) {
                uint32_t hp, lp;
                split2h(v0 * 0.25f, v1 * 0.25f, hp, lp);
                *(uint32_t*)(smc + QH_OFF + off) = hp;
                *(uint32_t*)(smc + QL_OFF + off) = lp;
                split2h(v2 * 0.25f, v3 * 0.25f, hp, lp);
                *(uint32_t*)(smc + QH_OFF + off + 8 * PITCHB) = hp;
                *(uint32_t*)(smc + QL_OFF + off + 8 * PITCHB) = lp;
            } else {
                uint32_t pofs = (s == 1) ? KP_OFF : VP_OFF;
                *(uint32_t*)(smc + pofs + off)              = packh(v0, v1);
                *(uint32_t*)(smc + pofs + off + 8 * PITCHB) = packh(v2, v3);
            }
        }
    }
    __syncthreads();   // q/k/v complete

    // ---- attention: unit (h,mt); warp handles heads g6, g6+2, g6+4 ----
    const float* maskb = mask + (size_t)(b % nW) * 4096;
    uint32_t oah[3][4], oal[3][4];   // own O tiles in proj-A fragment form
    #pragma unroll 1
    for (int iu = 0; iu < 3; iu++) {
        const int h = g6 + 2 * iu;
        const int r0 = mt * 16 + (lane >> 2);

        uint32_t qhf[4], qlf[4];
        {
            uint32_t ar = (uint32_t)(mt * 16 + (lane & 15)) * PITCHB
                        + (uint32_t)(h * 16 + ((lane >> 4) << 3)) * 2;
            ldsm_x4(qhf, sb + QH_OFF + ar);
            ldsm_x4(qlf, sb + QL_OFF + ar);
        }
        float s8[8][4];
        #pragma unroll
        for (int ntp = 0; ntp < 4; ntp++) {
            uint32_t kh[4];
            uint32_t br = (uint32_t)(ntp * 16 + (lane & 15)) * PITCHB
                        + (uint32_t)(h * 16 + ((lane >> 4) << 3)) * 2;
            ldsm_x4(kh, sb + KP_OFF + br);
            #pragma unroll
            for (int half = 0; half < 2; half++) {
                int nt = 2 * ntp + half;
                s8[nt][0] = 0.f; s8[nt][1] = 0.f; s8[nt][2] = 0.f; s8[nt][3] = 0.f;
                mma_h(s8[nt], qhf, kh[half], kh[half + 2]);
                mma_h(s8[nt], qlf, kh[half], kh[half + 2]);
            }
        }
        // + bias (fp16 table) + mask
        {
            const uint32_t* br0 = (const uint32_t*)(g_biash + (size_t)(h * 64 + r0) * 64);
            const uint32_t* br1 = (const uint32_t*)(g_biash + (size_t)(h * 64 + r0 + 8) * 64);
            const float2* mr0 = (const float2*)(maskb + (size_t)r0 * 64);
            const float2* mr1 = (const float2*)(maskb + (size_t)(r0 + 8) * 64);
            int ci = lane & 3;
            #pragma unroll
            for (int nt = 0; nt < 8; nt++) {
                uint32_t bw = br0[nt * 4 + ci];
                float2 bb = __half22float2(*reinterpret_cast<__half2*>(&bw));
                float2 mm = mr0[nt * 4 + ci];
                s8[nt][0] += bb.x + mm.x; s8[nt][1] += bb.y + mm.y;
                bw = br1[nt * 4 + ci];
                bb = __half22float2(*reinterpret_cast<__half2*>(&bw));
                mm = mr1[nt * 4 + ci];
                s8[nt][2] += bb.x + mm.x; s8[nt][3] += bb.y + mm.y;
            }
        }
        // softmax (register + shfl over lane%4 group)
        float mx0 = -1e30f, mx1 = -1e30f;
        #pragma unroll
        for (int nt = 0; nt < 8; nt++) {
            mx0 = fmaxf(mx0, fmaxf(s8[nt][0], s8[nt][1]));
            mx1 = fmaxf(mx1, fmaxf(s8[nt][2], s8[nt][3]));
        }
        mx0 = fmaxf(mx0, __shfl_xor_sync(0xffffffffu, mx0, 1));
        mx0 = fmaxf(mx0, __shfl_xor_sync(0xffffffffu, mx0, 2));
        mx1 = fmaxf(mx1, __shfl_xor_sync(0xffffffffu, mx1, 1));
        mx1 = fmaxf(mx1, __shfl_xor_sync(0xffffffffu, mx1, 2));
        float sum0 = 0.f, sum1 = 0.f;
        #pragma unroll
        for (int nt = 0; nt < 8; nt++) {
            s8[nt][0] = __expf(s8[nt][0] - mx0); sum0 += s8[nt][0];
            s8[nt][1] = __expf(s8[nt][1] - mx0); sum0 += s8[nt][1];
            s8[nt][2] = __expf(s8[nt][2] - mx1); sum1 += s8[nt][2];
            s8[nt][3] = __expf(s8[nt][3] - mx1); sum1 += s8[nt][3];
        }
        sum0 += __shfl_xor_sync(0xffffffffu, sum0, 1);
        sum0 += __shfl_xor_sync(0xffffffffu, sum0, 2);
        sum1 += __shfl_xor_sync(0xffffffffu, sum1, 1);
        sum1 += __shfl_xor_sync(0xffffffffu, sum1, 2);
        float inv0 = 1.f / sum0, inv1 = 1.f / sum1;
        #pragma unroll
        for (int nt = 0; nt < 8; nt++) {
            s8[nt][0] *= inv0; s8[nt][1] *= inv0;
            s8[nt][2] *= inv1; s8[nt][3] *= inv1;
        }
        // PV: O(16x16) = P(16x64) @ V(64x16); P single fp16, V single fp16
        float o[2][4];
        o[0][0]=0.f;o[0][1]=0.f;o[0][2]=0.f;o[0][3]=0.f;
        o[1][0]=0.f;o[1][1]=0.f;o[1][2]=0.f;o[1][3]=0.f;
        #pragma unroll
        for (int kt = 0; kt < 4; kt++) {
            uint32_t pa[4];
            pa[0] = packh(s8[2*kt][0],   s8[2*kt][1]);
            pa[1] = packh(s8[2*kt][2],   s8[2*kt][3]);
            pa[2] = packh(s8[2*kt+1][0], s8[2*kt+1][1]);
            pa[3] = packh(s8[2*kt+1][2], s8[2*kt+1][3]);
            uint32_t vr = (uint32_t)(kt * 16 + (lane & 15)) * PITCHB
                        + (uint32_t)(h * 16 + ((lane >> 4) << 3)) * 2;
            uint32_t vh[4];
            ldsm_x4t(vh, sb + VP_OFF + vr);
            mma_h(o[0], pa, vh[0], vh[1]);
            mma_h(o[1], pa, vh[2], vh[3]);
        }
        // split O hi/lo; keep in regs AND store into dead q tile (disjoint cols per warp)
        #pragma unroll
        for (int nt2 = 0; nt2 < 2; nt2++) {
            int c0 = h * 16 + nt2 * 8 + (lane & 3) * 2;
            uint32_t hp0, lp0, hp1, lp1;
            split2h(o[nt2][0], o[nt2][1], hp0, lp0);
            split2h(o[nt2][2], o[nt2][3], hp1, lp1);
            oah[iu][nt2*2]   = hp0; oal[iu][nt2*2]   = lp0;
            oah[iu][nt2*2+1] = hp1; oal[iu][nt2*2+1] = lp1;
            uint32_t off = (uint32_t)r0 * PITCHB + c0 * 2;
            *(uint32_t*)(smc + QH_OFF + off) = hp0;
            *(uint32_t*)(smc + QL_OFF + off) = lp0;
            off += 8 * PITCHB;
            *(uint32_t*)(smc + QH_OFF + off) = hp1;
            *(uint32_t*)(smc + QL_OFF + off) = lp1;
        }
    }
    __syncthreads();   // O complete in QH/QL planes

    // ---- proj GEMM: A = O (own tiles in regs, partner's via ldsm); B single fp16 ----
    {
        float acc[6][4];
        #pragma unroll
        for (int j = 0; j < 6; j++)
            { acc[j][0] = 0.f; acc[j][1] = 0.f; acc[j][2] = 0.f; acc[j][3] = 0.f; }
        #pragma unroll
        for (int kt = 0; kt < 6; kt++) {
            uint32_t ah[4], al[4];
            if ((kt & 1) == g6) {
                int iu = kt >> 1;
                ah[0] = oah[iu][0]; ah[1] = oah[iu][1]; ah[2] = oah[iu][2]; ah[3] = oah[iu][3];
                al[0] = oal[iu][0]; al[1] = oal[iu][1]; al[2] = oal[iu][2]; al[3] = oal[iu][3];
            } else {
                uint32_t ar = (uint32_t)(mt * 16 + (lane & 15)) * PITCHB
                            + (uint32_t)(kt * 16 + ((lane >> 4) << 3)) * 2;
                ldsm_x4(ah, sb + QH_OFF + ar);
                ldsm_x4(al, sb + QL_OFF + ar);
            }
            #pragma unroll
            for (int jp = 0; jp < 3; jp++) {
                int fi = (kt * 6 + g6 * 3 + jp) * 32 + lane;
                uint4 w = g_pwf4[fi];
                mma_h(acc[2*jp],   ah, w.x, w.y);
                mma_h(acc[2*jp],   al, w.x, w.y);
                mma_h(acc[2*jp+1], ah, w.z, w.w);
                mma_h(acc[2*jp+1], al, w.z, w.w);
            }
        }
        float* ob = out + (size_t)b * 6144;
        const int r0 = mt * 16 + (lane >> 2);
        #pragma unroll
        for (int j = 0; j < 6; j++) {
            int c0 = (g6 * 6 + j) * 8 + (lane & 3) * 2;
            float b0 = __ldg(proj_b + c0), b1 = __ldg(proj_b + c0 + 1);
            *(float2*)(ob + (size_t)r0 * 96 + c0) =
                make_float2(acc[j][0] + b0, acc[j][1] + b1);
            *(float2*)(ob + (size_t)(r0 + 8) * 96 + c0) =
                make_float2(acc[j][2] + b0, acc[j][3] + b1);
        }
    }
}

extern "C" void kernel_launch(void* const* d_in, const int* in_sizes, int n_in,
                              void* d_out, int out_size) {
    const float* x      = (const float*)d_in[0];
    const float* mask   = (const float*)d_in[1];
    const float* qkv_w  = (const float*)d_in[2];
    const float* qkv_b  = (const float*)d_in[3];
    const float* proj_w = (const float*)d_in[4];
    const float* proj_b = (const float*)d_in[5];
    const float* rpb    = (const float*)d_in[6];
    const int*   ridx   = (const int*)d_in[7];
    float* out = (float*)d_out;

    const int B_ = in_sizes[0] / (N_TOK * DIM);        // 8192
    const int nW = in_sizes[1] / (N_TOK * N_TOK);      // 512

    prep_kernel<<<114, 256>>>(qkv_w, proj_w, rpb, ridx);

    cudaFuncSetAttribute(win_attn_mma,
                         cudaFuncAttributeMaxDynamicSharedMemorySize, SMEM_BYTES);
    win_attn_mma<<<B_, THREADS, SMEM_BYTES>>>(x, mask, qkv_b, proj_b, out, nW);
}

// round 11
// speedup vs baseline: 6.0772x; 1.2352x over previous
#include <cuda_runtime.h>
#include <cuda_fp16.h>
#include <cstdint>

#define THREADS 256
#define N_TOK   64
#define DIM     96
#define HEADS   6

#define PITCHB  208u    // bytes per smem row (104 fp16; 13*16B, conflict-free LDSM)

// ---- smem planes: q hi, q lo, k, v  (QH plane becomes O in-place) ----
#define QH_OFF   0u
#define QL_OFF   13312u
#define KP_OFF   26624u
#define VP_OFF   39936u
#define SMEM_BYTES 53248u   // 2 CTAs/SM

// ---- prepped globals: weights in mma B-fragment order (single fp16 plane) ----
__device__ uint4  g_qwf4[3456];   // 3 slices * 6 kt * 6 np * 32 lanes
__device__ uint4  g_pwf4[1152];   // 6 kt * 6 np * 32 lanes
__device__ __half g_biash[HEADS * 64 * 64]; // [h][n][m] fp16

__device__ __forceinline__ uint32_t packh(float a, float b) {
    __half2 v;
    v.x = __float2half_rn(a);
    v.y = __float2half_rn(b);
    return *reinterpret_cast<uint32_t*>(&v);
}
__device__ __forceinline__ void split2h(float v0, float v1, uint32_t& hp, uint32_t& lp) {
    __half h0 = __float2half_rn(v0), h1 = __float2half_rn(v1);
    __half l0 = __float2half_rn(v0 - __half2float(h0));
    __half l1 = __float2half_rn(v1 - __half2float(h1));
    __half2 hh, ll;
    hh.x = h0; hh.y = h1; ll.x = l0; ll.y = l1;
    hp = *reinterpret_cast<uint32_t*>(&hh);
    lp = *reinterpret_cast<uint32_t*>(&ll);
}

__global__ void __launch_bounds__(256)
prep_kernel(const float* __restrict__ qkv_w, const float* __restrict__ proj_w,
            const float* __restrict__ rpb, const int* __restrict__ ridx)
{
    int idx = blockIdx.x * 256 + threadIdx.x;
    if (idx < 3456) {
        int lane = idx & 31, np = (idx >> 5) % 6, kt = (idx / 192) % 6, s = idx / 1152;
        int k0 = kt * 16 + (lane & 3) * 2;
        int nc0 = (2 * np) * 8 + (lane >> 2);
        int nc1 = nc0 + 8;
        const float* w0 = qkv_w + s * 96 + nc0;
        const float* w1 = qkv_w + s * 96 + nc1;
        uint4 r;
        r.x = packh(w0[(k0)     * 288], w0[(k0 + 1) * 288]);
        r.y = packh(w0[(k0 + 8) * 288], w0[(k0 + 9) * 288]);
        r.z = packh(w1[(k0)     * 288], w1[(k0 + 1) * 288]);
        r.w = packh(w1[(k0 + 8) * 288], w1[(k0 + 9) * 288]);
        g_qwf4[idx] = r;
    } else if (idx < 4608) {
        int j = idx - 3456;
        int lane = j & 31, np = (j >> 5) % 6, kt = j / 192;
        int k0 = kt * 16 + (lane & 3) * 2;
        int nc0 = (2 * np) * 8 + (lane >> 2);
        int nc1 = nc0 + 8;
        const float* w0 = proj_w + nc0;
        const float* w1 = proj_w + nc1;
        uint4 r;
        r.x = packh(w0[(k0)     * 96], w0[(k0 + 1) * 96]);
        r.y = packh(w0[(k0 + 8) * 96], w0[(k0 + 9) * 96]);
        r.z = packh(w1[(k0)     * 96], w1[(k0 + 1) * 96]);
        r.w = packh(w1[(k0 + 8) * 96], w1[(k0 + 9) * 96]);
        g_pwf4[j] = r;
    } else if (idx < 4608 + 24576) {
        int j = idx - 4608;
        int h = j >> 12, r = (j >> 6) & 63, m = j & 63;
        g_biash[j] = __float2half_rn(rpb[ridx[r * 64 + m] * HEADS + h]);
    }
}

// ---- PTX helpers ----
__device__ __forceinline__ uint32_t smem_u32(const void* p) {
    uint32_t a;
    asm("{ .reg .u64 t; cvta.to.shared.u64 t, %1; cvt.u32.u64 %0, t; }" : "=r"(a) : "l"(p));
    return a;
}
__device__ __forceinline__ void ldsm_x4(uint32_t* r, uint32_t a) {
    asm volatile("ldmatrix.sync.aligned.m8n8.x4.shared.b16 {%0,%1,%2,%3}, [%4];"
        : "=r"(r[0]), "=r"(r[1]), "=r"(r[2]), "=r"(r[3]) : "r"(a));
}
__device__ __forceinline__ void ldsm_x4t(uint32_t* r, uint32_t a) {
    asm volatile("ldmatrix.sync.aligned.m8n8.x4.trans.shared.b16 {%0,%1,%2,%3}, [%4];"
        : "=r"(r[0]), "=r"(r[1]), "=r"(r[2]), "=r"(r[3]) : "r"(a));
}
__device__ __forceinline__ void mma_h(float* c, const uint32_t* a,
                                      uint32_t b0, uint32_t b1) {
    asm volatile("mma.sync.aligned.m16n8k16.row.col.f32.f16.f16.f32 "
        "{%0,%1,%2,%3}, {%4,%5,%6,%7}, {%8,%9}, {%0,%1,%2,%3};"
        : "+f"(c[0]), "+f"(c[1]), "+f"(c[2]), "+f"(c[3])
        : "r"(a[0]), "r"(a[1]), "r"(a[2]), "r"(a[3]), "r"(b0), "r"(b1));
}

extern __shared__ char smc[];

__global__ void __launch_bounds__(THREADS, 2)
win_attn_mma(const float* __restrict__ x,
             const float* __restrict__ mask,
             const float* __restrict__ qkv_b,
             const float* __restrict__ proj_b,
             float* __restrict__ out,
             int nW)
{
    const int t = threadIdx.x, wid = t >> 5, lane = t & 31, b = blockIdx.x;
    const uint32_t sb = smem_u32(smc);
    const int mt = wid & 3;      // m tile 0..3
    const int g6 = wid >> 2;     // n group 0..1

    // ---- load A fragments (x) from gmem, fp16 split ----
    uint32_t xah[6][4], xal[6][4];
    {
        const float* xb = x + (size_t)b * 6144;
        const int gr = lane >> 2, ck = (lane & 3) * 2;
        const float* base = xb + (size_t)(mt * 16 + gr) * 96 + ck;
        #pragma unroll
        for (int kt = 0; kt < 6; kt++) {
            float2 v00 = *(const float2*)(base + kt * 16);
            float2 v10 = *(const float2*)(base + kt * 16 + 8 * 96);
            float2 v01 = *(const float2*)(base + kt * 16 + 8);
            float2 v11 = *(const float2*)(base + kt * 16 + 8 * 96 + 8);
            split2h(v00.x, v00.y, xah[kt][0], xal[kt][0]);
            split2h(v10.x, v10.y, xah[kt][1], xal[kt][1]);
            split2h(v01.x, v01.y, xah[kt][2], xal[kt][2]);
            split2h(v11.x, v11.y, xah[kt][3], xal[kt][3]);
        }
    }
    const int r0 = mt * 16 + (lane >> 2);

    // ---- q slice (s=0): A hi+lo (full precision feed into softmax chain) ----
    {
        float acc[6][4];
        #pragma unroll
        for (int j = 0; j < 6; j++)
            { acc[j][0] = 0.f; acc[j][1] = 0.f; acc[j][2] = 0.f; acc[j][3] = 0.f; }
        #pragma unroll
        for (int kt = 0; kt < 6; kt++) {
            #pragma unroll
            for (int jp = 0; jp < 3; jp++) {
                int fi = (kt * 6 + g6 * 3 + jp) * 32 + lane;
                uint4 w = g_qwf4[fi];
                mma_h(acc[2*jp],   xah[kt], w.x, w.y);
                mma_h(acc[2*jp],   xal[kt], w.x, w.y);
                mma_h(acc[2*jp+1], xah[kt], w.z, w.w);
                mma_h(acc[2*jp+1], xal[kt], w.z, w.w);
            }
        }
        #pragma unroll
        for (int j = 0; j < 6; j++) {
            int c0 = (g6 * 6 + j) * 8 + (lane & 3) * 2;
            float b0 = __ldg(qkv_b + c0), b1 = __ldg(qkv_b + c0 + 1);
            uint32_t off = (uint32_t)r0 * PITCHB + c0 * 2;
            uint32_t hp, lp;
            split2h((acc[j][0] + b0) * 0.25f, (acc[j][1] + b1) * 0.25f, hp, lp);
            *(uint32_t*)(smc + QH_OFF + off) = hp;
            *(uint32_t*)(smc + QL_OFF + off) = lp;
            split2h((acc[j][2] + b0) * 0.25f, (acc[j][3] + b1) * 0.25f, hp, lp);
            *(uint32_t*)(smc + QH_OFF + off + 8 * PITCHB) = hp;
            *(uint32_t*)(smc + QL_OFF + off + 8 * PITCHB) = lp;
        }
    }

    // ---- k,v slices (s=1,2): A hi only (results rounded to fp16 anyway) ----
    #pragma unroll 1
    for (int s = 1; s < 3; s++) {
        float acc[6][4];
        #pragma unroll
        for (int j = 0; j < 6; j++)
            { acc[j][0] = 0.f; acc[j][1] = 0.f; acc[j][2] = 0.f; acc[j][3] = 0.f; }
        #pragma unroll
        for (int kt = 0; kt < 6; kt++) {
            #pragma unroll
            for (int jp = 0; jp < 3; jp++) {
                int fi = ((s * 6 + kt) * 6 + g6 * 3 + jp) * 32 + lane;
                uint4 w = g_qwf4[fi];
                mma_h(acc[2*jp],   xah[kt], w.x, w.y);
                mma_h(acc[2*jp+1], xah[kt], w.z, w.w);
            }
        }
        uint32_t pofs = (s == 1) ? KP_OFF : VP_OFF;
        #pragma unroll
        for (int j = 0; j < 6; j++) {
            int c0 = (g6 * 6 + j) * 8 + (lane & 3) * 2;
            float b0 = __ldg(qkv_b + s * 96 + c0), b1 = __ldg(qkv_b + s * 96 + c0 + 1);
            uint32_t off = (uint32_t)r0 * PITCHB + c0 * 2;
            *(uint32_t*)(smc + pofs + off)              = packh(acc[j][0] + b0, acc[j][1] + b1);
            *(uint32_t*)(smc + pofs + off + 8 * PITCHB) = packh(acc[j][2] + b0, acc[j][3] + b1);
        }
    }
    __syncthreads();   // q/k/v complete

    // ---- attention: warp handles heads g6, g6+2, g6+4 on its mt tile ----
    const float* maskb = mask + (size_t)(b % nW) * 4096;
    uint32_t oah[3][4];              // own O tiles in proj-A fragment form (single fp16)
    #pragma unroll 1
    for (int iu = 0; iu < 3; iu++) {
        const int h = g6 + 2 * iu;

        uint32_t qhf[4], qlf[4];
        {
            uint32_t ar = (uint32_t)(mt * 16 + (lane & 15)) * PITCHB
                        + (uint32_t)(h * 16 + ((lane >> 4) << 3)) * 2;
            ldsm_x4(qhf, sb + QH_OFF + ar);
            ldsm_x4(qlf, sb + QL_OFF + ar);
        }
        float s8[8][4];
        #pragma unroll
        for (int ntp = 0; ntp < 4; ntp++) {
            uint32_t kh[4];
            uint32_t br = (uint32_t)(ntp * 16 + (lane & 15)) * PITCHB
                        + (uint32_t)(h * 16 + ((lane >> 4) << 3)) * 2;
            ldsm_x4(kh, sb + KP_OFF + br);
            #pragma unroll
            for (int half = 0; half < 2; half++) {
                int nt = 2 * ntp + half;
                s8[nt][0] = 0.f; s8[nt][1] = 0.f; s8[nt][2] = 0.f; s8[nt][3] = 0.f;
                mma_h(s8[nt], qhf, kh[half], kh[half + 2]);
                mma_h(s8[nt], qlf, kh[half], kh[half + 2]);
            }
        }
        // + bias (fp16 table) + mask
        {
            const uint32_t* br0 = (const uint32_t*)(g_biash + (size_t)(h * 64 + r0) * 64);
            const uint32_t* br1 = (const uint32_t*)(g_biash + (size_t)(h * 64 + r0 + 8) * 64);
            const float2* mr0 = (const float2*)(maskb + (size_t)r0 * 64);
            const float2* mr1 = (const float2*)(maskb + (size_t)(r0 + 8) * 64);
            int ci = lane & 3;
            #pragma unroll
            for (int nt = 0; nt < 8; nt++) {
                uint32_t bw = br0[nt * 4 + ci];
                float2 bb = __half22float2(*reinterpret_cast<__half2*>(&bw));
                float2 mm = mr0[nt * 4 + ci];
                s8[nt][0] += bb.x + mm.x; s8[nt][1] += bb.y + mm.y;
                bw = br1[nt * 4 + ci];
                bb = __half22float2(*reinterpret_cast<__half2*>(&bw));
                mm = mr1[nt * 4 + ci];
                s8[nt][2] += bb.x + mm.x; s8[nt][3] += bb.y + mm.y;
            }
        }
        // softmax (register + shfl over lane%4 group)
        float mx0 = -1e30f, mx1 = -1e30f;
        #pragma unroll
        for (int nt = 0; nt < 8; nt++) {
            mx0 = fmaxf(mx0, fmaxf(s8[nt][0], s8[nt][1]));
            mx1 = fmaxf(mx1, fmaxf(s8[nt][2], s8[nt][3]));
        }
        mx0 = fmaxf(mx0, __shfl_xor_sync(0xffffffffu, mx0, 1));
        mx0 = fmaxf(mx0, __shfl_xor_sync(0xffffffffu, mx0, 2));
        mx1 = fmaxf(mx1, __shfl_xor_sync(0xffffffffu, mx1, 1));
        mx1 = fmaxf(mx1, __shfl_xor_sync(0xffffffffu, mx1, 2));
        float sum0 = 0.f, sum1 = 0.f;
        #pragma unroll
        for (int nt = 0; nt < 8; nt++) {
            s8[nt][0] = __expf(s8[nt][0] - mx0); sum0 += s8[nt][0];
            s8[nt][1] = __expf(s8[nt][1] - mx0); sum0 += s8[nt][1];
            s8[nt][2] = __expf(s8[nt][2] - mx1); sum1 += s8[nt][2];
            s8[nt][3] = __expf(s8[nt][3] - mx1); sum1 += s8[nt][3];
        }
        sum0 += __shfl_xor_sync(0xffffffffu, sum0, 1);
        sum0 += __shfl_xor_sync(0xffffffffu, sum0, 2);
        sum1 += __shfl_xor_sync(0xffffffffu, sum1, 1);
        sum1 += __shfl_xor_sync(0xffffffffu, sum1, 2);
        float inv0 = 1.f / sum0, inv1 = 1.f / sum1;
        #pragma unroll
        for (int nt = 0; nt < 8; nt++) {
            s8[nt][0] *= inv0; s8[nt][1] *= inv0;
            s8[nt][2] *= inv1; s8[nt][3] *= inv1;
        }
        // PV: O(16x16) = P(16x64) @ V(64x16); P,V single fp16
        float o[2][4];
        o[0][0]=0.f;o[0][1]=0.f;o[0][2]=0.f;o[0][3]=0.f;
        o[1][0]=0.f;o[1][1]=0.f;o[1][2]=0.f;o[1][3]=0.f;
        #pragma unroll
        for (int kt = 0; kt < 4; kt++) {
            uint32_t pa[4];
            pa[0] = packh(s8[2*kt][0],   s8[2*kt][1]);
            pa[1] = packh(s8[2*kt][2],   s8[2*kt][3]);
            pa[2] = packh(s8[2*kt+1][0], s8[2*kt+1][1]);
            pa[3] = packh(s8[2*kt+1][2], s8[2*kt+1][3]);
            uint32_t vr = (uint32_t)(kt * 16 + (lane & 15)) * PITCHB
                        + (uint32_t)(h * 16 + ((lane >> 4) << 3)) * 2;
            uint32_t vh[4];
            ldsm_x4t(vh, sb + VP_OFF + vr);
            mma_h(o[0], pa, vh[0], vh[1]);
            mma_h(o[1], pa, vh[2], vh[3]);
        }
        // O single fp16: keep in regs AND store into dead q-hi tile
        #pragma unroll
        for (int nt2 = 0; nt2 < 2; nt2++) {
            int c0 = h * 16 + nt2 * 8 + (lane & 3) * 2;
            uint32_t p0 = packh(o[nt2][0], o[nt2][1]);
            uint32_t p1 = packh(o[nt2][2], o[nt2][3]);
            oah[iu][nt2*2]   = p0;
            oah[iu][nt2*2+1] = p1;
            uint32_t off = (uint32_t)r0 * PITCHB + c0 * 2;
            *(uint32_t*)(smc + QH_OFF + off)              = p0;
            *(uint32_t*)(smc + QH_OFF + off + 8 * PITCHB) = p1;
        }
    }
    __syncthreads();   // O complete in QH plane

    // ---- proj GEMM: A = O single fp16 (own tiles in regs, partner via ldsm) ----
    {
        float acc[6][4];
        #pragma unroll
        for (int j = 0; j < 6; j++)
            { acc[j][0] = 0.f; acc[j][1] = 0.f; acc[j][2] = 0.f; acc[j][3] = 0.f; }
        #pragma unroll
        for (int kt = 0; kt < 6; kt++) {
            uint32_t ah[4];
            if ((kt & 1) == g6) {
                int iu = kt >> 1;
                ah[0] = oah[iu][0]; ah[1] = oah[iu][1]; ah[2] = oah[iu][2]; ah[3] = oah[iu][3];
            } else {
                uint32_t ar = (uint32_t)(mt * 16 + (lane & 15)) * PITCHB
                            + (uint32_t)(kt * 16 + ((lane >> 4) << 3)) * 2;
                ldsm_x4(ah, sb + QH_OFF + ar);
            }
            #pragma unroll
            for (int jp = 0; jp < 3; jp++) {
                int fi = (kt * 6 + g6 * 3 + jp) * 32 + lane;
                uint4 w = g_pwf4[fi];
                mma_h(acc[2*jp],   ah, w.x, w.y);
                mma_h(acc[2*jp+1], ah, w.z, w.w);
            }
        }
        float* ob = out + (size_t)b * 6144;
        #pragma unroll
        for (int j = 0; j < 6; j++) {
            int c0 = (g6 * 6 + j) * 8 + (lane & 3) * 2;
            float b0 = __ldg(proj_b + c0), b1 = __ldg(proj_b + c0 + 1);
            *(float2*)(ob + (size_t)r0 * 96 + c0) =
                make_float2(acc[j][0] + b0, acc[j][1] + b1);
            *(float2*)(ob + (size_t)(r0 + 8) * 96 + c0) =
                make_float2(acc[j][2] + b0, acc[j][3] + b1);
        }
    }
}

extern "C" void kernel_launch(void* const* d_in, const int* in_sizes, int n_in,
                              void* d_out, int out_size) {
    const float* x      = (const float*)d_in[0];
    const float* mask   = (const float*)d_in[1];
    const float* qkv_w  = (const float*)d_in[2];
    const float* qkv_b  = (const float*)d_in[3];
    const float* proj_w = (const float*)d_in[4];
    const float* proj_b = (const float*)d_in[5];
    const float* rpb    = (const float*)d_in[6];
    const int*   ridx   = (const int*)d_in[7];
    float* out = (float*)d_out;

    const int B_ = in_sizes[0] / (N_TOK * DIM);        // 8192
    const int nW = in_sizes[1] / (N_TOK * N_TOK);      // 512

    prep_kernel<<<114, 256>>>(qkv_w, proj_w, rpb, ridx);

    cudaFuncSetAttribute(win_attn_mma,
                         cudaFuncAttributeMaxDynamicSharedMemorySize, SMEM_BYTES);
    win_attn_mma<<<B_, THREADS, SMEM_BYTES>>>(x, mask, qkv_b, proj_b, out, nW);
}